// round 8
// baseline (speedup 1.0000x reference)
#include <cuda_runtime.h>
#include <math.h>
#include <stdint.h>

// Problem dims: B=8, T=1024, E=1024, H=16, HD=64, FF=4096, M = B*T = 8192

// ---------------- scratch (device globals; no allocations allowed) ----------
__device__ float g_qkv[(size_t)8192 * 3072];
__device__ float g_attn[(size_t)8192 * 1024];
__device__ float g_s[(size_t)8192 * 1024];
__device__ float g_x1[(size_t)8192 * 1024];    // LN1 out (unrounded, residual)
__device__ float g_x1r[(size_t)8192 * 1024];   // LN1 out (tf32-rounded, operand)
__device__ float g_ff[(size_t)8192 * 4096];
__device__ float g_xr[(size_t)8192 * 1024];    // x, tf32-rounded (operand)
__device__ float g_wq[12582912];               // rounded weights (see offsets)
__device__ int   g_len[8];
// g_wq offsets (floats): in_w 0, out_w 3145728, fc1_w 4194304, fc2_w 8388608

// ---------------- padding-mask dtype detection + length extraction ----------
__global__ void mask_len_kernel(const void* mask) {
    __shared__ int sGT1, sEQ1, sF32;
    if (threadIdx.x == 0) { sGT1 = 0; sEQ1 = 0; sF32 = 0; }
    __syncthreads();
    const unsigned int* w = (const unsigned int*)mask;
    int gt1 = 0, eq1 = 0, f32 = 0;
    for (int i = threadIdx.x; i < 2048; i += 256) {
        unsigned int v = w[i];
        if (v == 0x3F800000u)      f32 = 1;
        else if (v == 1u)          eq1 = 1;
        else if (v != 0u)          gt1 = 1;
    }
    if (f32) atomicOr(&sF32, 1);
    if (gt1) atomicOr(&sGT1, 1);
    if (eq1) atomicOr(&sEQ1, 1);
    __syncthreads();
    if (threadIdx.x < 8) {
        const int b = threadIdx.x;
        int len = 1024;
        if (sF32) {
            const float* p = (const float*)mask;
            for (int k = 0; k < 1024; ++k)
                if (p[(size_t)b * 1024 + k] != 0.f) { len = k; break; }
        } else if (sGT1) {
            const unsigned char* p = (const unsigned char*)mask;
            for (int k = 0; k < 1024; ++k)
                if (p[(size_t)b * 1024 + k]) { len = k; break; }
        } else if (sEQ1) {
            const int* p = (const int*)mask;
            for (int k = 0; k < 1024; ++k)
                if (p[(size_t)b * 1024 + k]) { len = k; break; }
        }
        g_len[b] = len;
    }
}

// ---------------- common helpers -------------------------------------------
__device__ __forceinline__ uint32_t f2tf(float x) {
    uint32_t r;
    asm("cvt.rna.tf32.f32 %0, %1;" : "=r"(r) : "f"(x));
    return r;
}
__device__ __forceinline__ void mma_tf32(float* d, const uint32_t* a, const uint32_t* b) {
    asm volatile(
        "mma.sync.aligned.m16n8k8.row.col.f32.tf32.tf32.f32 "
        "{%0,%1,%2,%3}, {%4,%5,%6,%7}, {%8,%9}, {%0,%1,%2,%3};"
        : "+f"(d[0]), "+f"(d[1]), "+f"(d[2]), "+f"(d[3])
        : "r"(a[0]), "r"(a[1]), "r"(a[2]), "r"(a[3]), "r"(b[0]), "r"(b[1]));
}
__device__ __forceinline__ void ldsm4(uint32_t& r0, uint32_t& r1, uint32_t& r2, uint32_t& r3,
                                      uint32_t addr) {
    asm volatile("ldmatrix.sync.aligned.m8n8.x4.shared.b16 {%0,%1,%2,%3}, [%4];"
                 : "=r"(r0), "=r"(r1), "=r"(r2), "=r"(r3) : "r"(addr));
}
__device__ __forceinline__ uint32_t s2u(const void* p) {
    return (uint32_t)__cvta_generic_to_shared(p);
}
__device__ __forceinline__ void cpasync16(uint32_t dst, const void* src) {
    asm volatile("cp.async.cg.shared.global [%0], [%1], 16;"
                 :: "r"(dst), "l"(src) : "memory");
}

// ---------------- tf32 RNA pre-rounding pass --------------------------------
__global__ __launch_bounds__(256) void cvt_tf32_kernel(
    const float* __restrict__ src, float* __restrict__ dst, int n4)
{
    int i = blockIdx.x * 256 + threadIdx.x;
    if (i < n4) {
        float4 v = ((const float4*)src)[i];
        float4 o;
        o.x = __uint_as_float(f2tf(v.x));
        o.y = __uint_as_float(f2tf(v.y));
        o.z = __uint_as_float(f2tf(v.z));
        o.w = __uint_as_float(f2tf(v.w));
        ((float4*)dst)[i] = o;
    }
}

// ---------------- tf32 tensor-core GEMM (cp.async, kstep 32, 3 stages) ------
// C[M,N] = A[M,K] @ W[N,K]^T + bias (+res/+relu).
// 128x128 tile, kstep 32 (rows = 128B), 8 warps (4m x 2n), warp tile 32x64.
// Inputs are pre-rounded to tf32 in GMEM, so HMMA's RZ truncation is exact.
// SMEM: 3 stages x (A 16KB + B 16KB); full-row XOR swizzle: chunk c of row r
// at byte r*128 + 16*(c ^ (r&7)).  One barrier per 64 mmas.
template <int EPI, bool ROUND_OUT>  // EPI 0: +bias, 1: +bias+res, 2: +bias+relu
__global__ __launch_bounds__(256, 2) void tgemm_kernel(
    const float* __restrict__ A, const float* __restrict__ W,
    const float* __restrict__ bias, const float* __restrict__ R,
    float* __restrict__ C, int Ksz, int Nsz)
{
    extern __shared__ uint32_t smem[];   // 3 x 32KB = 96KB
    const uint32_t sbase = s2u(smem);

    const int tid  = threadIdx.x;
    const int lane = tid & 31;
    const int warp = tid >> 5;
    const int wm   = warp & 3;
    const int wn   = warp >> 2;
    const int m0   = blockIdx.y * 128;
    const int n0   = blockIdx.x * 128;

    // staging: thread t -> row t>>1 (0..127), chunks 4h..4h+3 (h = t&1)
    const int srow = tid >> 1;
    const int sh   = tid & 1;
    uint32_t dA[4];
#pragma unroll
    for (int i = 0; i < 4; ++i) {
        int c = sh * 4 + i;
        dA[i] = srow * 128 + 16 * (c ^ (srow & 7));
    }
    const float* asrc = A + (size_t)(m0 + srow) * Ksz + sh * 16;
    const float* bsrc = W + (size_t)(n0 + srow) * Ksz + sh * 16;

    // fragment constants
    const int mat = lane >> 3, rr = lane & 7;
    const int ar  = wm * 32 + (mat & 1) * 8 + rr;       // A rows (tile0; +16 tile1)
    const int cbA = mat >> 1;
    const int rmA = ar & 7;
    const uint32_t rowA = (uint32_t)ar * 128;
    const int br  = wn * 64 + (mat >> 1) * 8 + rr;      // B rows (jp tiles +16)
    const int cbB = mat & 1;
    const int rmB = br & 7;
    const uint32_t rowB = 16384u + (uint32_t)br * 128;

    float acc[2][8][4];
#pragma unroll
    for (int i = 0; i < 2; ++i)
#pragma unroll
        for (int j = 0; j < 8; ++j)
#pragma unroll
            for (int r = 0; r < 4; ++r) acc[i][j][r] = 0.f;

    const int KT = Ksz >> 5;             // k-tiles of 32

    // prologue: stages 0,1
#pragma unroll
    for (int p = 0; p < 2; ++p) {
        const uint32_t st = sbase + p * 32768;
#pragma unroll
        for (int i = 0; i < 4; ++i) {
            cpasync16(st + dA[i],          asrc + p * 32 + i * 4);
            cpasync16(st + 16384 + dA[i],  bsrc + p * 32 + i * 4);
        }
        asm volatile("cp.async.commit_group;" ::: "memory");
    }

    int stg = 0;                          // kt % 3
    for (int kt = 0; kt < KT; ++kt) {
        asm volatile("cp.async.wait_group 1;" ::: "memory");
        __syncthreads();

        // prefetch stage kt+2 (buffer == (kt-1)%3; its reads finished pre-barrier)
        if (kt + 2 < KT) {
            int ps = stg + 2; if (ps >= 3) ps -= 3;
            const uint32_t st = sbase + ps * 32768;
#pragma unroll
            for (int i = 0; i < 4; ++i) {
                cpasync16(st + dA[i],         asrc + (kt + 2) * 32 + i * 4);
                cpasync16(st + 16384 + dA[i], bsrc + (kt + 2) * 32 + i * 4);
            }
        }
        asm volatile("cp.async.commit_group;" ::: "memory");

        const uint32_t sgA = sbase + stg * 32768 + rowA;
        const uint32_t sgB = sbase + stg * 32768 + rowB;
#pragma unroll
        for (int ks = 0; ks < 4; ++ks) {
            const uint32_t oa = sgA + 16 * ((2 * ks + cbA) ^ rmA);
            uint32_t af0[4], af1[4];
            ldsm4(af0[0], af0[1], af0[2], af0[3], oa);
            ldsm4(af1[0], af1[1], af1[2], af1[3], oa + 2048);
            const uint32_t ob = sgB + 16 * ((2 * ks + cbB) ^ rmB);
#pragma unroll
            for (int jp = 0; jp < 4; ++jp) {
                uint32_t bf[4];
                ldsm4(bf[0], bf[1], bf[2], bf[3], ob + jp * 2048);
                mma_tf32(acc[0][2 * jp],     af0, &bf[0]);
                mma_tf32(acc[1][2 * jp],     af1, &bf[0]);
                mma_tf32(acc[0][2 * jp + 1], af0, &bf[2]);
                mma_tf32(acc[1][2 * jp + 1], af1, &bf[2]);
            }
        }
        if (++stg == 3) stg = 0;
    }

    // epilogue
#pragma unroll
    for (int i = 0; i < 2; ++i) {
        int row = m0 + wm * 32 + i * 16 + (lane >> 2);
#pragma unroll
        for (int j = 0; j < 8; ++j) {
            int col = n0 + wn * 64 + j * 8 + (lane & 3) * 2;
            float b0v = bias[col], b1v = bias[col + 1];
            size_t o0 = (size_t)row * Nsz + col;
            size_t o1 = (size_t)(row + 8) * Nsz + col;
            float v0 = acc[i][j][0] + b0v, v1 = acc[i][j][1] + b1v;
            float v2 = acc[i][j][2] + b0v, v3 = acc[i][j][3] + b1v;
            if (EPI == 1) {
                v0 += R[o0]; v1 += R[o0 + 1];
                v2 += R[o1]; v3 += R[o1 + 1];
            }
            if (EPI == 2) {
                v0 = fmaxf(v0, 0.f); v1 = fmaxf(v1, 0.f);
                v2 = fmaxf(v2, 0.f); v3 = fmaxf(v3, 0.f);
            }
            if (ROUND_OUT) {
                v0 = __uint_as_float(f2tf(v0)); v1 = __uint_as_float(f2tf(v1));
                v2 = __uint_as_float(f2tf(v2)); v3 = __uint_as_float(f2tf(v3));
            }
            float2 q0v = { v0, v1 }, q1v = { v2, v3 };
            *(float2*)&C[o0] = q0v;
            *(float2*)&C[o1] = q1v;
        }
    }
}

// ---------------- attention: tf32-mma flash, per (b, h, 64-query tile) ------
__device__ __forceinline__ uint32_t aswz(uint32_t base, int row, int chunk) {
    int pos = (chunk & 8) | ((chunk & 7) ^ (row & 7));
    return base + (row * 64 + 4 * pos) * 4;
}

__global__ __launch_bounds__(128) void attn_kernel(
    const float* __restrict__ qkv, const int* __restrict__ lenv,
    float* __restrict__ out)
{
    __shared__ uint32_t Qs[64 * 64];
    __shared__ uint32_t KP[64 * 64];
    __shared__ uint32_t Vt[64 * 64];

    const int tid  = threadIdx.x;
    const int lane = tid & 31;
    const int wrp  = tid >> 5;
    const int b    = blockIdx.z;
    const int h    = blockIdx.y;
    const int qt   = blockIdx.x;
    const int q0   = qt * 64;
    const int blen = lenv[b];
    const float scale = 0.125f;

    const uint32_t Qb = s2u(Qs), Kb = s2u(KP), Vb = s2u(Vt);

    for (int i = tid; i < 64 * 16; i += 128) {
        int r = i >> 4, c4 = i & 15;
        float4 v = *(const float4*)&qkv[(size_t)(b * 1024 + q0 + r) * 3072 + h * 64 + c4 * 4];
        int pos = (c4 & 8) | ((c4 & 7) ^ (r & 7));
        uint32_t t[4] = { f2tf(v.x * scale), f2tf(v.y * scale),
                          f2tf(v.z * scale), f2tf(v.w * scale) };
        *(uint4*)&Qs[r * 64 + 4 * pos] = *(uint4*)t;
    }

    const int mat = lane >> 3, rr = lane & 7;
    const int g   = lane >> 2;
    const int q2  = lane & 3;
    const int aRowQ = wrp * 16 + (mat & 1) * 8 + rr;
    const int cbitA = mat >> 1;
    const int cbitB = mat & 1;
    const int bRowOff = (mat >> 1) * 8 + rr;

    float O[8][4];
    float m0r = -1e30f, m1r = -1e30f, l0r = 0.f, l1r = 0.f;
#pragma unroll
    for (int j = 0; j < 8; ++j)
#pragma unroll
        for (int r = 0; r < 4; ++r) O[j][r] = 0.f;

    const int ktmax = qt;
    for (int kt = 0; kt <= ktmax && kt * 64 < blen; ++kt) {
        const int k0 = kt * 64;
        __syncthreads();

        for (int i = tid; i < 64 * 16; i += 128) {
            int r = i >> 4, c4 = i & 15;
            float4 v = *(const float4*)&qkv[(size_t)(b * 1024 + k0 + r) * 3072 + 1024 + h * 64 + c4 * 4];
            int pos = (c4 & 8) | ((c4 & 7) ^ (r & 7));
            uint32_t t[4] = { f2tf(v.x), f2tf(v.y), f2tf(v.z), f2tf(v.w) };
            *(uint4*)&KP[r * 64 + 4 * pos] = *(uint4*)t;
        }
        for (int i = tid; i < 64 * 16; i += 128) {
            int key = i & 63, dc = i >> 6;
            float4 v = *(const float4*)&qkv[(size_t)(b * 1024 + k0 + key) * 3072 + 2048 + h * 64 + dc * 4];
            int kc = key >> 2, kb = key & 3;
            float e[4] = { v.x, v.y, v.z, v.w };
#pragma unroll
            for (int s = 0; s < 4; ++s) {
                int d = dc * 4 + s;
                int pos = (kc & 8) | ((kc & 7) ^ (d & 7));
                Vt[d * 64 + 4 * pos + kb] = f2tf(e[s]);
            }
        }
        __syncthreads();

        float s[8][4];
#pragma unroll
        for (int j = 0; j < 8; ++j)
#pragma unroll
            for (int r = 0; r < 4; ++r) s[j][r] = 0.f;

#pragma unroll
        for (int kk = 0; kk < 8; ++kk) {
            int ck = kk * 2;
            uint32_t af[4];
            ldsm4(af[0], af[1], af[2], af[3], aswz(Qb, aRowQ, ck + cbitA));
#pragma unroll
            for (int jp = 0; jp < 4; ++jp) {
                uint32_t bf[4];
                ldsm4(bf[0], bf[1], bf[2], bf[3],
                      aswz(Kb, jp * 16 + bRowOff, ck + cbitB));
                mma_tf32(s[2 * jp],     af, &bf[0]);
                mma_tf32(s[2 * jp + 1], af, &bf[2]);
            }
        }

        const int qr0 = q0 + wrp * 16 + g;
        const int qr1 = qr0 + 8;
#pragma unroll
        for (int j = 0; j < 8; ++j) {
            int c0 = k0 + j * 8 + q2 * 2;
            int c1 = c0 + 1;
            if (c0 > qr0 || c0 >= blen) s[j][0] = -1e30f;
            if (c1 > qr0 || c1 >= blen) s[j][1] = -1e30f;
            if (c0 > qr1 || c0 >= blen) s[j][2] = -1e30f;
            if (c1 > qr1 || c1 >= blen) s[j][3] = -1e30f;
        }
        float mx0 = -1e30f, mx1 = -1e30f;
#pragma unroll
        for (int j = 0; j < 8; ++j) {
            mx0 = fmaxf(mx0, fmaxf(s[j][0], s[j][1]));
            mx1 = fmaxf(mx1, fmaxf(s[j][2], s[j][3]));
        }
        mx0 = fmaxf(mx0, __shfl_xor_sync(0xffffffffu, mx0, 1));
        mx0 = fmaxf(mx0, __shfl_xor_sync(0xffffffffu, mx0, 2));
        mx1 = fmaxf(mx1, __shfl_xor_sync(0xffffffffu, mx1, 1));
        mx1 = fmaxf(mx1, __shfl_xor_sync(0xffffffffu, mx1, 2));
        float mn0 = fmaxf(m0r, mx0), mn1 = fmaxf(m1r, mx1);
        float al0 = __expf(m0r - mn0), al1 = __expf(m1r - mn1);
        float sm0 = 0.f, sm1 = 0.f;
#pragma unroll
        for (int j = 0; j < 8; ++j) {
            s[j][0] = __expf(s[j][0] - mn0);
            s[j][1] = __expf(s[j][1] - mn0);
            s[j][2] = __expf(s[j][2] - mn1);
            s[j][3] = __expf(s[j][3] - mn1);
            sm0 += s[j][0] + s[j][1];
            sm1 += s[j][2] + s[j][3];
        }
        sm0 += __shfl_xor_sync(0xffffffffu, sm0, 1);
        sm0 += __shfl_xor_sync(0xffffffffu, sm0, 2);
        sm1 += __shfl_xor_sync(0xffffffffu, sm1, 1);
        sm1 += __shfl_xor_sync(0xffffffffu, sm1, 2);
        l0r = l0r * al0 + sm0;
        l1r = l1r * al1 + sm1;
        m0r = mn0; m1r = mn1;
#pragma unroll
        for (int j = 0; j < 8; ++j) {
            O[j][0] *= al0; O[j][1] *= al0;
            O[j][2] *= al1; O[j][3] *= al1;
        }

        __syncthreads();
#pragma unroll
        for (int j = 0; j < 8; ++j) {
            int key = j * 8 + q2 * 2;
            int kc  = key >> 2;
            int pos = (kc & 8) | ((kc & 7) ^ (g & 7));
            int wrd = (wrp * 16 + g) * 64 + 4 * pos + (key & 3);
            uint32_t p0[2] = { f2tf(s[j][0]), f2tf(s[j][1]) };
            *(uint2*)&KP[wrd] = *(uint2*)p0;
            uint32_t p1[2] = { f2tf(s[j][2]), f2tf(s[j][3]) };
            *(uint2*)&KP[wrd + 8 * 64] = *(uint2*)p1;
        }
        __syncthreads();

#pragma unroll
        for (int kk = 0; kk < 8; ++kk) {
            int ck = kk * 2;
            uint32_t af[4];
            ldsm4(af[0], af[1], af[2], af[3], aswz(Kb, aRowQ, ck + cbitA));
#pragma unroll
            for (int jp = 0; jp < 4; ++jp) {
                uint32_t bf[4];
                ldsm4(bf[0], bf[1], bf[2], bf[3],
                      aswz(Vb, jp * 16 + bRowOff, ck + cbitB));
                mma_tf32(O[2 * jp],     af, &bf[0]);
                mma_tf32(O[2 * jp + 1], af, &bf[2]);
            }
        }
    }

    // epilogue: normalize, round to tf32 (it feeds the out-proj GEMM), write
    const float inv0 = 1.f / l0r, inv1 = 1.f / l1r;
    const int row0 = b * 1024 + q0 + wrp * 16 + g;
#pragma unroll
    for (int j = 0; j < 8; ++j) {
        int d = h * 64 + j * 8 + q2 * 2;
        float2 v0 = { __uint_as_float(f2tf(O[j][0] * inv0)),
                      __uint_as_float(f2tf(O[j][1] * inv0)) };
        float2 v1 = { __uint_as_float(f2tf(O[j][2] * inv1)),
                      __uint_as_float(f2tf(O[j][3] * inv1)) };
        *(float2*)&out[(size_t)row0 * 1024 + d] = v0;
        *(float2*)&out[(size_t)(row0 + 8) * 1024 + d] = v1;
    }
}

// ---------------- LayerNorm (optional second, tf32-rounded output) ----------
__global__ __launch_bounds__(256) void ln_kernel(
    const float* __restrict__ X, const float* __restrict__ w,
    const float* __restrict__ bb, float* __restrict__ Y,
    float* __restrict__ Yr)
{
    const int row = blockIdx.x;
    const int t   = threadIdx.x;
    float4 x = *(const float4*)&X[(size_t)row * 1024 + t * 4];
    float s = x.x + x.y + x.z + x.w;
    float q = fmaf(x.x, x.x, fmaf(x.y, x.y, fmaf(x.z, x.z, x.w * x.w)));
#pragma unroll
    for (int off = 16; off; off >>= 1) {
        s += __shfl_xor_sync(0xffffffffu, s, off);
        q += __shfl_xor_sync(0xffffffffu, q, off);
    }
    __shared__ float ss[8], qq[8];
    const int warp = t >> 5, lane = t & 31;
    if (lane == 0) { ss[warp] = s; qq[warp] = q; }
    __syncthreads();
    float S = 0.f, Q2 = 0.f;
#pragma unroll
    for (int i = 0; i < 8; ++i) { S += ss[i]; Q2 += qq[i]; }
    const float mean = S * (1.0f / 1024.0f);
    const float var  = fmaxf(Q2 * (1.0f / 1024.0f) - mean * mean, 0.f);
    const float inv  = rsqrtf(var + 1e-12f);
    float4 wv = *(const float4*)&w[t * 4];
    float4 bv = *(const float4*)&bb[t * 4];
    float4 y;
    y.x = wv.x * (x.x - mean) * inv + bv.x;
    y.y = wv.y * (x.y - mean) * inv + bv.y;
    y.z = wv.z * (x.z - mean) * inv + bv.z;
    y.w = wv.w * (x.w - mean) * inv + bv.w;
    *(float4*)&Y[(size_t)row * 1024 + t * 4] = y;
    if (Yr) {
        float4 yr;
        yr.x = __uint_as_float(f2tf(y.x));
        yr.y = __uint_as_float(f2tf(y.y));
        yr.z = __uint_as_float(f2tf(y.z));
        yr.w = __uint_as_float(f2tf(y.w));
        *(float4*)&Yr[(size_t)row * 1024 + t * 4] = yr;
    }
}

// ---------------- launch ----------------------------------------------------
static constexpr int TG_SMEM = 98304;   // 3 stages x 32KB

extern "C" void kernel_launch(void* const* d_in, const int* in_sizes, int n_in,
                              void* d_out, int out_size)
{
    const float* x     = (const float*)d_in[0];
    const float* in_w  = (const float*)d_in[1];
    const float* in_b  = (const float*)d_in[2];
    const float* out_w = (const float*)d_in[3];
    const float* out_b = (const float*)d_in[4];
    const float* fc1_w = (const float*)d_in[5];
    const float* fc1_b = (const float*)d_in[6];
    const float* fc2_w = (const float*)d_in[7];
    const float* fc2_b = (const float*)d_in[8];
    const float* ln1_w = (const float*)d_in[9];
    const float* ln1_b = (const float*)d_in[10];
    const float* ln2_w = (const float*)d_in[11];
    const float* ln2_b = (const float*)d_in[12];
    const void*  pad   = d_in[13];
    float* out = (float*)d_out;

    float *qkv, *attn, *sbuf, *x1, *x1r, *ff, *xr, *wq;
    int* lenv;
    cudaGetSymbolAddress((void**)&qkv,  g_qkv);
    cudaGetSymbolAddress((void**)&attn, g_attn);
    cudaGetSymbolAddress((void**)&sbuf, g_s);
    cudaGetSymbolAddress((void**)&x1,   g_x1);
    cudaGetSymbolAddress((void**)&x1r,  g_x1r);
    cudaGetSymbolAddress((void**)&ff,   g_ff);
    cudaGetSymbolAddress((void**)&xr,   g_xr);
    cudaGetSymbolAddress((void**)&wq,   g_wq);
    cudaGetSymbolAddress((void**)&lenv, g_len);

    float* w_in  = wq;
    float* w_out = wq + 3145728;
    float* w_f1  = wq + 4194304;
    float* w_f2  = wq + 8388608;

    static bool attr_done = false;
    if (!attr_done) {
        cudaFuncSetAttribute(tgemm_kernel<0, false>, cudaFuncAttributeMaxDynamicSharedMemorySize, TG_SMEM);
        cudaFuncSetAttribute(tgemm_kernel<1, false>, cudaFuncAttributeMaxDynamicSharedMemorySize, TG_SMEM);
        cudaFuncSetAttribute(tgemm_kernel<2, true>,  cudaFuncAttributeMaxDynamicSharedMemorySize, TG_SMEM);
        attr_done = true;
    }

    mask_len_kernel<<<1, 256>>>(pad);
    // pre-round operands to tf32 (removes RZ-truncation bias in the GEMMs)
    cvt_tf32_kernel<<<8192, 256>>>(x,     xr,    2097152);
    cvt_tf32_kernel<<<3072, 256>>>(in_w,  w_in,   786432);
    cvt_tf32_kernel<<<1024, 256>>>(out_w, w_out,  262144);
    cvt_tf32_kernel<<<4096, 256>>>(fc1_w, w_f1,  1048576);
    cvt_tf32_kernel<<<4096, 256>>>(fc2_w, w_f2,  1048576);

    // 1) qkv = xr @ in_w^T + in_b          [8192, 3072]
    tgemm_kernel<0, false><<<dim3(24, 64), 256, TG_SMEM>>>(xr, w_in, in_b, nullptr, qkv, 1024, 3072);
    // 2) attention -> attn (tf32-rounded)  [8192, 1024]
    attn_kernel<<<dim3(16, 16, 8), 128>>>(qkv, lenv, attn);
    // 3) s1 = attn @ out_w^T + out_b + x   [8192, 1024]
    tgemm_kernel<1, false><<<dim3(8, 64), 256, TG_SMEM>>>(attn, w_out, out_b, x, sbuf, 1024, 1024);
    // 4) x1 = LN1(s1); x1r = tf32(x1)
    ln_kernel<<<8192, 256>>>(sbuf, ln1_w, ln1_b, x1, x1r);
    // 5) ff = relu(x1r @ fc1_w^T + fc1_b) (tf32-rounded)  [8192, 4096]
    tgemm_kernel<2, true><<<dim3(32, 64), 256, TG_SMEM>>>(x1r, w_f1, fc1_b, nullptr, ff, 1024, 4096);
    // 6) s2 = ff @ fc2_w^T + fc2_b + x1    [8192, 1024]
    tgemm_kernel<1, false><<<dim3(8, 64), 256, TG_SMEM>>>(ff, w_f2, fc2_b, x1, sbuf, 4096, 1024);
    // 7) out = LN2(s2)
    ln_kernel<<<8192, 256>>>(sbuf, ln2_w, ln2_b, out, nullptr);
}

// round 9
// speedup vs baseline: 1.1858x; 1.1858x over previous
#include <cuda_runtime.h>
#include <math.h>
#include <stdint.h>

// Problem dims: B=8, T=1024, E=1024, H=16, HD=64, FF=4096, M = B*T = 8192

// ---------------- scratch (device globals; no allocations allowed) ----------
__device__ float g_qkv[(size_t)8192 * 3072];
__device__ float g_attn[(size_t)8192 * 1024];
__device__ float g_s[(size_t)8192 * 1024];
__device__ float g_x1[(size_t)8192 * 1024];
__device__ float g_ff[(size_t)8192 * 4096];
__device__ float g_wq[12582912];   // rounded weights: in_w 0, out_w 3145728, fc1_w 4194304, fc2_w 8388608
__device__ int   g_len[8];

// ---------------- padding-mask dtype detection + length extraction ----------
__global__ void mask_len_kernel(const void* mask) {
    __shared__ int sGT1, sEQ1, sF32;
    if (threadIdx.x == 0) { sGT1 = 0; sEQ1 = 0; sF32 = 0; }
    __syncthreads();
    const unsigned int* w = (const unsigned int*)mask;
    int gt1 = 0, eq1 = 0, f32 = 0;
    for (int i = threadIdx.x; i < 2048; i += 256) {
        unsigned int v = w[i];
        if (v == 0x3F800000u)      f32 = 1;
        else if (v == 1u)          eq1 = 1;
        else if (v != 0u)          gt1 = 1;
    }
    if (f32) atomicOr(&sF32, 1);
    if (gt1) atomicOr(&sGT1, 1);
    if (eq1) atomicOr(&sEQ1, 1);
    __syncthreads();
    if (threadIdx.x < 8) {
        const int b = threadIdx.x;
        int len = 1024;
        if (sF32) {
            const float* p = (const float*)mask;
            for (int k = 0; k < 1024; ++k)
                if (p[(size_t)b * 1024 + k] != 0.f) { len = k; break; }
        } else if (sGT1) {
            const unsigned char* p = (const unsigned char*)mask;
            for (int k = 0; k < 1024; ++k)
                if (p[(size_t)b * 1024 + k]) { len = k; break; }
        } else if (sEQ1) {
            const int* p = (const int*)mask;
            for (int k = 0; k < 1024; ++k)
                if (p[(size_t)b * 1024 + k]) { len = k; break; }
        }
        g_len[b] = len;
    }
}

// ---------------- common helpers -------------------------------------------
__device__ __forceinline__ uint32_t f2tf(float x) {
    uint32_t r;
    asm("cvt.rna.tf32.f32 %0, %1;" : "=r"(r) : "f"(x));
    return r;
}
__device__ __forceinline__ void mma_tf32(float* d, const uint32_t* a, const uint32_t* b) {
    asm volatile(
        "mma.sync.aligned.m16n8k8.row.col.f32.tf32.tf32.f32 "
        "{%0,%1,%2,%3}, {%4,%5,%6,%7}, {%8,%9}, {%0,%1,%2,%3};"
        : "+f"(d[0]), "+f"(d[1]), "+f"(d[2]), "+f"(d[3])
        : "r"(a[0]), "r"(a[1]), "r"(a[2]), "r"(a[3]), "r"(b[0]), "r"(b[1]));
}
__device__ __forceinline__ void ldsm4(uint32_t& r0, uint32_t& r1, uint32_t& r2, uint32_t& r3,
                                      uint32_t addr) {
    asm volatile("ldmatrix.sync.aligned.m8n8.x4.shared.b16 {%0,%1,%2,%3}, [%4];"
                 : "=r"(r0), "=r"(r1), "=r"(r2), "=r"(r3) : "r"(addr));
}
__device__ __forceinline__ uint32_t s2u(const void* p) {
    return (uint32_t)__cvta_generic_to_shared(p);
}
__device__ __forceinline__ void cpasync16(uint32_t dst, const void* src) {
    asm volatile("cp.async.cg.shared.global [%0], [%1], 16;"
                 :: "r"(dst), "l"(src) : "memory");
}

// ---------------- tf32 RNA pre-rounding pass (weights only) -----------------
__global__ __launch_bounds__(256) void cvt_tf32_kernel(
    const float* __restrict__ src, float* __restrict__ dst, int n4)
{
    int i = blockIdx.x * 256 + threadIdx.x;
    if (i < n4) {
        float4 v = ((const float4*)src)[i];
        float4 o;
        o.x = __uint_as_float(f2tf(v.x));
        o.y = __uint_as_float(f2tf(v.y));
        o.z = __uint_as_float(f2tf(v.z));
        o.w = __uint_as_float(f2tf(v.w));
        ((float4*)dst)[i] = o;
    }
}

// ---------------- tf32 tensor-core GEMM (cp.async, 128x64 tile, 3 CTA/SM) ---
// C[M,N] = A[M,K] @ W[N,K]^T + bias (+res/+relu).
// CTA tile 128(M)x64(N), kstep 16, 8 warps (4m x 2n), warp tile 32x32.
// 32 accumulators/thread (~75 regs) -> 3 CTAs/SM = 24 warps (was 16): the
// R7 profile was occupancy-bound (occ 21%, issue 18%, tensor 54%).
// SMEM: 4 stages x 12KB (A 8KB + B 4KB); chunk swizzle: 16B chunk c of row r
// at byte r*64 + 16*(c ^ ((r>>1)&3)).  Pipeline identical to R7: one barrier
// per k-tile, wait_group 2, prefetch kt+3.
template <int EPI, bool ROUND_OUT>  // EPI 0: +bias, 1: +bias+res, 2: +bias+relu
__global__ __launch_bounds__(256, 3) void tgemm_kernel(
    const float* __restrict__ A, const float* __restrict__ W,
    const float* __restrict__ bias, const float* __restrict__ R,
    float* __restrict__ C, int Ksz, int Nsz)
{
    extern __shared__ uint32_t smem[];   // 4 stages x 12KB = 48KB
    const uint32_t sbase = s2u(smem);

    const int tid  = threadIdx.x;
    const int lane = tid & 31;
    const int warp = tid >> 5;
    const int wm   = warp & 3;          // 4 m-tiles of 32
    const int wn   = warp >> 2;         // 2 n-tiles of 32
    const int m0   = blockIdx.y * 128;
    const int n0   = blockIdx.x * 64;

    // staging: 3 cp.async/thread/stage.  i=0,1 -> A (rows tid>>2 halves), i=2 -> B
    const float* srcp[3];
    uint32_t     dsto[3];
#pragma unroll
    for (int i = 0; i < 3; ++i) {
        int idx = i * 256 + tid;
        if (idx < 512) {                 // A: 128 rows x 4 chunks
            int row = idx >> 2, c = idx & 3;
            srcp[i] = A + (size_t)(m0 + row) * Ksz + c * 4;
            dsto[i] = row * 64 + 16 * (c ^ ((row >> 1) & 3));
        } else {                         // B: 64 rows x 4 chunks
            int j = idx - 512;
            int row = j >> 2, c = j & 3;
            srcp[i] = W + (size_t)(n0 + row) * Ksz + c * 4;
            dsto[i] = 8192 + row * 64 + 16 * (c ^ ((row >> 1) & 3));
        }
    }

    // fragment ldmatrix base addresses (stage 0, kk=0)
    const int mat = lane >> 3, rr = lane & 7;
    const int ar  = wm * 32 + (mat & 1) * 8 + rr;
    const int cbA = mat >> 1;
    const uint32_t aA = sbase + ar * 64 + 16 * (cbA ^ ((ar >> 1) & 3));
    const int br  = wn * 32 + (mat >> 1) * 8 + rr;
    const int cbB = mat & 1;
    const uint32_t aB = sbase + 8192 + br * 64 + 16 * (cbB ^ ((br >> 1) & 3));

    float acc[2][4][4];
#pragma unroll
    for (int i = 0; i < 2; ++i)
#pragma unroll
        for (int j = 0; j < 4; ++j)
#pragma unroll
            for (int r = 0; r < 4; ++r) acc[i][j][r] = 0.f;

    const int KT = Ksz >> 4;             // k-steps of 16

    // prologue: stages 0..2
#pragma unroll
    for (int p = 0; p < 3; ++p) {
        const uint32_t st = p * 12288;
#pragma unroll
        for (int i = 0; i < 3; ++i)
            cpasync16(sbase + st + dsto[i], srcp[i] + p * 16);
        asm volatile("cp.async.commit_group;" ::: "memory");
    }

    for (int kt = 0; kt < KT; ++kt) {
        asm volatile("cp.async.wait_group 2;" ::: "memory");
        __syncthreads();

        if (kt + 3 < KT) {
            const uint32_t st = ((kt + 3) & 3) * 12288;
#pragma unroll
            for (int i = 0; i < 3; ++i)
                cpasync16(sbase + st + dsto[i], srcp[i] + (kt + 3) * 16);
        }
        asm volatile("cp.async.commit_group;" ::: "memory");

        const uint32_t off = (kt & 3) * 12288;
        const uint32_t aAb = aA + off;
        const uint32_t aBb = aB + off;
#pragma unroll
        for (int kk8 = 0; kk8 < 2; ++kk8) {
            const uint32_t xo = kk8 << 5;        // kk=8 -> XOR 32 bytes
            uint32_t af0[4], af1[4];
            ldsm4(af0[0], af0[1], af0[2], af0[3], aAb ^ xo);
            ldsm4(af1[0], af1[1], af1[2], af1[3], (aAb + 1024) ^ xo);
#pragma unroll
            for (int jp = 0; jp < 2; ++jp) {
                uint32_t bf[4];
                ldsm4(bf[0], bf[1], bf[2], bf[3], (aBb + jp * 1024) ^ xo);
                mma_tf32(acc[0][2 * jp],     af0, &bf[0]);
                mma_tf32(acc[1][2 * jp],     af1, &bf[0]);
                mma_tf32(acc[0][2 * jp + 1], af0, &bf[2]);
                mma_tf32(acc[1][2 * jp + 1], af1, &bf[2]);
            }
        }
    }

    // epilogue
#pragma unroll
    for (int i = 0; i < 2; ++i) {
        int row = m0 + wm * 32 + i * 16 + (lane >> 2);
#pragma unroll
        for (int j = 0; j < 4; ++j) {
            int col = n0 + wn * 32 + j * 8 + (lane & 3) * 2;
            float b0v = bias[col], b1v = bias[col + 1];
            size_t o0 = (size_t)row * Nsz + col;
            size_t o1 = (size_t)(row + 8) * Nsz + col;
            float v0 = acc[i][j][0] + b0v, v1 = acc[i][j][1] + b1v;
            float v2 = acc[i][j][2] + b0v, v3 = acc[i][j][3] + b1v;
            if (EPI == 1) {
                v0 += R[o0]; v1 += R[o0 + 1];
                v2 += R[o1]; v3 += R[o1 + 1];
            }
            if (EPI == 2) {
                v0 = fmaxf(v0, 0.f); v1 = fmaxf(v1, 0.f);
                v2 = fmaxf(v2, 0.f); v3 = fmaxf(v3, 0.f);
            }
            if (ROUND_OUT) {
                v0 = __uint_as_float(f2tf(v0)); v1 = __uint_as_float(f2tf(v1));
                v2 = __uint_as_float(f2tf(v2)); v3 = __uint_as_float(f2tf(v3));
            }
            float2 q0v = { v0, v1 }, q1v = { v2, v3 };
            *(float2*)&C[o0] = q0v;
            *(float2*)&C[o1] = q1v;
        }
    }
}

// ---------------- attention: tf32-mma flash, per (b, h, 64-query tile) ------
__device__ __forceinline__ uint32_t aswz(uint32_t base, int row, int chunk) {
    int pos = (chunk & 8) | ((chunk & 7) ^ (row & 7));
    return base + (row * 64 + 4 * pos) * 4;
}

__global__ __launch_bounds__(128) void attn_kernel(
    const float* __restrict__ qkv, const int* __restrict__ lenv,
    float* __restrict__ out)
{
    __shared__ uint32_t Qs[64 * 64];
    __shared__ uint32_t KP[64 * 64];
    __shared__ uint32_t Vt[64 * 64];

    const int tid  = threadIdx.x;
    const int lane = tid & 31;
    const int wrp  = tid >> 5;
    const int b    = blockIdx.z;
    const int h    = blockIdx.y;
    const int qt   = blockIdx.x;
    const int q0   = qt * 64;
    const int blen = lenv[b];
    const float scale = 0.125f;

    const uint32_t Qb = s2u(Qs), Kb = s2u(KP), Vb = s2u(Vt);

    for (int i = tid; i < 64 * 16; i += 128) {
        int r = i >> 4, c4 = i & 15;
        float4 v = *(const float4*)&qkv[(size_t)(b * 1024 + q0 + r) * 3072 + h * 64 + c4 * 4];
        int pos = (c4 & 8) | ((c4 & 7) ^ (r & 7));
        uint32_t t[4] = { f2tf(v.x * scale), f2tf(v.y * scale),
                          f2tf(v.z * scale), f2tf(v.w * scale) };
        *(uint4*)&Qs[r * 64 + 4 * pos] = *(uint4*)t;
    }

    const int mat = lane >> 3, rr = lane & 7;
    const int g   = lane >> 2;
    const int q2  = lane & 3;
    const int aRowQ = wrp * 16 + (mat & 1) * 8 + rr;
    const int cbitA = mat >> 1;
    const int cbitB = mat & 1;
    const int bRowOff = (mat >> 1) * 8 + rr;

    float O[8][4];
    float m0r = -1e30f, m1r = -1e30f, l0r = 0.f, l1r = 0.f;
#pragma unroll
    for (int j = 0; j < 8; ++j)
#pragma unroll
        for (int r = 0; r < 4; ++r) O[j][r] = 0.f;

    const int ktmax = qt;
    for (int kt = 0; kt <= ktmax && kt * 64 < blen; ++kt) {
        const int k0 = kt * 64;
        __syncthreads();

        for (int i = tid; i < 64 * 16; i += 128) {
            int r = i >> 4, c4 = i & 15;
            float4 v = *(const float4*)&qkv[(size_t)(b * 1024 + k0 + r) * 3072 + 1024 + h * 64 + c4 * 4];
            int pos = (c4 & 8) | ((c4 & 7) ^ (r & 7));
            uint32_t t[4] = { f2tf(v.x), f2tf(v.y), f2tf(v.z), f2tf(v.w) };
            *(uint4*)&KP[r * 64 + 4 * pos] = *(uint4*)t;
        }
        for (int i = tid; i < 64 * 16; i += 128) {
            int key = i & 63, dc = i >> 6;
            float4 v = *(const float4*)&qkv[(size_t)(b * 1024 + k0 + key) * 3072 + 2048 + h * 64 + dc * 4];
            int kc = key >> 2, kb = key & 3;
            float e[4] = { v.x, v.y, v.z, v.w };
#pragma unroll
            for (int s = 0; s < 4; ++s) {
                int d = dc * 4 + s;
                int pos = (kc & 8) | ((kc & 7) ^ (d & 7));
                Vt[d * 64 + 4 * pos + kb] = f2tf(e[s]);
            }
        }
        __syncthreads();

        float s[8][4];
#pragma unroll
        for (int j = 0; j < 8; ++j)
#pragma unroll
            for (int r = 0; r < 4; ++r) s[j][r] = 0.f;

#pragma unroll
        for (int kk = 0; kk < 8; ++kk) {
            int ck = kk * 2;
            uint32_t af[4];
            ldsm4(af[0], af[1], af[2], af[3], aswz(Qb, aRowQ, ck + cbitA));
#pragma unroll
            for (int jp = 0; jp < 4; ++jp) {
                uint32_t bf[4];
                ldsm4(bf[0], bf[1], bf[2], bf[3],
                      aswz(Kb, jp * 16 + bRowOff, ck + cbitB));
                mma_tf32(s[2 * jp],     af, &bf[0]);
                mma_tf32(s[2 * jp + 1], af, &bf[2]);
            }
        }

        const int qr0 = q0 + wrp * 16 + g;
        const int qr1 = qr0 + 8;
#pragma unroll
        for (int j = 0; j < 8; ++j) {
            int c0 = k0 + j * 8 + q2 * 2;
            int c1 = c0 + 1;
            if (c0 > qr0 || c0 >= blen) s[j][0] = -1e30f;
            if (c1 > qr0 || c1 >= blen) s[j][1] = -1e30f;
            if (c0 > qr1 || c0 >= blen) s[j][2] = -1e30f;
            if (c1 > qr1 || c1 >= blen) s[j][3] = -1e30f;
        }
        float mx0 = -1e30f, mx1 = -1e30f;
#pragma unroll
        for (int j = 0; j < 8; ++j) {
            mx0 = fmaxf(mx0, fmaxf(s[j][0], s[j][1]));
            mx1 = fmaxf(mx1, fmaxf(s[j][2], s[j][3]));
        }
        mx0 = fmaxf(mx0, __shfl_xor_sync(0xffffffffu, mx0, 1));
        mx0 = fmaxf(mx0, __shfl_xor_sync(0xffffffffu, mx0, 2));
        mx1 = fmaxf(mx1, __shfl_xor_sync(0xffffffffu, mx1, 1));
        mx1 = fmaxf(mx1, __shfl_xor_sync(0xffffffffu, mx1, 2));
        float mn0 = fmaxf(m0r, mx0), mn1 = fmaxf(m1r, mx1);
        float al0 = __expf(m0r - mn0), al1 = __expf(m1r - mn1);
        float sm0 = 0.f, sm1 = 0.f;
#pragma unroll
        for (int j = 0; j < 8; ++j) {
            s[j][0] = __expf(s[j][0] - mn0);
            s[j][1] = __expf(s[j][1] - mn0);
            s[j][2] = __expf(s[j][2] - mn1);
            s[j][3] = __expf(s[j][3] - mn1);
            sm0 += s[j][0] + s[j][1];
            sm1 += s[j][2] + s[j][3];
        }
        sm0 += __shfl_xor_sync(0xffffffffu, sm0, 1);
        sm0 += __shfl_xor_sync(0xffffffffu, sm0, 2);
        sm1 += __shfl_xor_sync(0xffffffffu, sm1, 1);
        sm1 += __shfl_xor_sync(0xffffffffu, sm1, 2);
        l0r = l0r * al0 + sm0;
        l1r = l1r * al1 + sm1;
        m0r = mn0; m1r = mn1;
#pragma unroll
        for (int j = 0; j < 8; ++j) {
            O[j][0] *= al0; O[j][1] *= al0;
            O[j][2] *= al1; O[j][3] *= al1;
        }

        __syncthreads();
#pragma unroll
        for (int j = 0; j < 8; ++j) {
            int key = j * 8 + q2 * 2;
            int kc  = key >> 2;
            int pos = (kc & 8) | ((kc & 7) ^ (g & 7));
            int wrd = (wrp * 16 + g) * 64 + 4 * pos + (key & 3);
            uint32_t p0[2] = { f2tf(s[j][0]), f2tf(s[j][1]) };
            *(uint2*)&KP[wrd] = *(uint2*)p0;
            uint32_t p1[2] = { f2tf(s[j][2]), f2tf(s[j][3]) };
            *(uint2*)&KP[wrd + 8 * 64] = *(uint2*)p1;
        }
        __syncthreads();

#pragma unroll
        for (int kk = 0; kk < 8; ++kk) {
            int ck = kk * 2;
            uint32_t af[4];
            ldsm4(af[0], af[1], af[2], af[3], aswz(Kb, aRowQ, ck + cbitA));
#pragma unroll
            for (int jp = 0; jp < 4; ++jp) {
                uint32_t bf[4];
                ldsm4(bf[0], bf[1], bf[2], bf[3],
                      aswz(Vb, jp * 16 + bRowOff, ck + cbitB));
                mma_tf32(O[2 * jp],     af, &bf[0]);
                mma_tf32(O[2 * jp + 1], af, &bf[2]);
            }
        }
    }

    // epilogue: normalize, round to tf32 (feeds the out-proj GEMM exactly)
    const float inv0 = 1.f / l0r, inv1 = 1.f / l1r;
    const int row0 = b * 1024 + q0 + wrp * 16 + g;
#pragma unroll
    for (int j = 0; j < 8; ++j) {
        int d = h * 64 + j * 8 + q2 * 2;
        float2 v0 = { __uint_as_float(f2tf(O[j][0] * inv0)),
                      __uint_as_float(f2tf(O[j][1] * inv0)) };
        float2 v1 = { __uint_as_float(f2tf(O[j][2] * inv1)),
                      __uint_as_float(f2tf(O[j][3] * inv1)) };
        *(float2*)&out[(size_t)row0 * 1024 + d] = v0;
        *(float2*)&out[(size_t)(row0 + 8) * 1024 + d] = v1;
    }
}

// ---------------- LayerNorm ------------------------------------------------
__global__ __launch_bounds__(256) void ln_kernel(
    const float* __restrict__ X, const float* __restrict__ w,
    const float* __restrict__ bb, float* __restrict__ Y)
{
    const int row = blockIdx.x;
    const int t   = threadIdx.x;
    float4 x = *(const float4*)&X[(size_t)row * 1024 + t * 4];
    float s = x.x + x.y + x.z + x.w;
    float q = fmaf(x.x, x.x, fmaf(x.y, x.y, fmaf(x.z, x.z, x.w * x.w)));
#pragma unroll
    for (int off = 16; off; off >>= 1) {
        s += __shfl_xor_sync(0xffffffffu, s, off);
        q += __shfl_xor_sync(0xffffffffu, q, off);
    }
    __shared__ float ss[8], qq[8];
    const int warp = t >> 5, lane = t & 31;
    if (lane == 0) { ss[warp] = s; qq[warp] = q; }
    __syncthreads();
    float S = 0.f, Q2 = 0.f;
#pragma unroll
    for (int i = 0; i < 8; ++i) { S += ss[i]; Q2 += qq[i]; }
    const float mean = S * (1.0f / 1024.0f);
    const float var  = fmaxf(Q2 * (1.0f / 1024.0f) - mean * mean, 0.f);
    const float inv  = rsqrtf(var + 1e-12f);
    float4 wv = *(const float4*)&w[t * 4];
    float4 bv = *(const float4*)&bb[t * 4];
    float4 y;
    y.x = wv.x * (x.x - mean) * inv + bv.x;
    y.y = wv.y * (x.y - mean) * inv + bv.y;
    y.z = wv.z * (x.z - mean) * inv + bv.z;
    y.w = wv.w * (x.w - mean) * inv + bv.w;
    *(float4*)&Y[(size_t)row * 1024 + t * 4] = y;
}

// ---------------- launch ----------------------------------------------------
static constexpr int TG_SMEM = 49152;   // 4 stages x 12KB

extern "C" void kernel_launch(void* const* d_in, const int* in_sizes, int n_in,
                              void* d_out, int out_size)
{
    const float* x     = (const float*)d_in[0];
    const float* in_w  = (const float*)d_in[1];
    const float* in_b  = (const float*)d_in[2];
    const float* out_w = (const float*)d_in[3];
    const float* out_b = (const float*)d_in[4];
    const float* fc1_w = (const float*)d_in[5];
    const float* fc1_b = (const float*)d_in[6];
    const float* fc2_w = (const float*)d_in[7];
    const float* fc2_b = (const float*)d_in[8];
    const float* ln1_w = (const float*)d_in[9];
    const float* ln1_b = (const float*)d_in[10];
    const float* ln2_w = (const float*)d_in[11];
    const float* ln2_b = (const float*)d_in[12];
    const void*  pad   = d_in[13];
    float* out = (float*)d_out;

    float *qkv, *attn, *sbuf, *x1, *ff, *wq;
    int* lenv;
    cudaGetSymbolAddress((void**)&qkv,  g_qkv);
    cudaGetSymbolAddress((void**)&attn, g_attn);
    cudaGetSymbolAddress((void**)&sbuf, g_s);
    cudaGetSymbolAddress((void**)&x1,   g_x1);
    cudaGetSymbolAddress((void**)&ff,   g_ff);
    cudaGetSymbolAddress((void**)&wq,   g_wq);
    cudaGetSymbolAddress((void**)&lenv, g_len);

    float* w_in  = wq;
    float* w_out = wq + 3145728;
    float* w_f1  = wq + 4194304;
    float* w_f2  = wq + 8388608;

    static bool attr_done = false;
    if (!attr_done) {
        cudaFuncSetAttribute(tgemm_kernel<0, false>, cudaFuncAttributeMaxDynamicSharedMemorySize, TG_SMEM);
        cudaFuncSetAttribute(tgemm_kernel<1, false>, cudaFuncAttributeMaxDynamicSharedMemorySize, TG_SMEM);
        cudaFuncSetAttribute(tgemm_kernel<2, true>,  cudaFuncAttributeMaxDynamicSharedMemorySize, TG_SMEM);
        attr_done = true;
    }

    mask_len_kernel<<<1, 256>>>(pad);
    // pre-round weights to tf32 (RNA); activations rounded by producing kernels
    cvt_tf32_kernel<<<3072, 256>>>(in_w,  w_in,   786432);
    cvt_tf32_kernel<<<1024, 256>>>(out_w, w_out,  262144);
    cvt_tf32_kernel<<<4096, 256>>>(fc1_w, w_f1,  1048576);
    cvt_tf32_kernel<<<4096, 256>>>(fc2_w, w_f2,  1048576);

    // 1) qkv = x @ in_w^T + in_b           [8192, 3072]
    tgemm_kernel<0, false><<<dim3(48, 64), 256, TG_SMEM>>>(x, w_in, in_b, nullptr, qkv, 1024, 3072);
    // 2) attention -> attn (tf32-rounded)  [8192, 1024]
    attn_kernel<<<dim3(16, 16, 8), 128>>>(qkv, lenv, attn);
    // 3) s1 = attn @ out_w^T + out_b + x   [8192, 1024]  (both operands exact tf32)
    tgemm_kernel<1, false><<<dim3(16, 64), 256, TG_SMEM>>>(attn, w_out, out_b, x, sbuf, 1024, 1024);
    // 4) x1 = LN1(s1)
    ln_kernel<<<8192, 256>>>(sbuf, ln1_w, ln1_b, x1);
    // 5) ff = relu(x1 @ fc1_w^T + fc1_b) (tf32-rounded)  [8192, 4096]
    tgemm_kernel<2, true><<<dim3(64, 64), 256, TG_SMEM>>>(x1, w_f1, fc1_b, nullptr, ff, 1024, 4096);
    // 6) s2 = ff @ fc2_w^T + fc2_b + x1    [8192, 1024]  (both operands exact tf32)
    tgemm_kernel<1, false><<<dim3(16, 64), 256, TG_SMEM>>>(ff, w_f2, fc2_b, x1, sbuf, 4096, 1024);
    // 7) out = LN2(s2)
    ln_kernel<<<8192, 256>>>(sbuf, ln2_w, ln2_b, out);
}

// round 10
// speedup vs baseline: 1.2336x; 1.0403x over previous
#include <cuda_runtime.h>
#include <math.h>
#include <stdint.h>

// Problem dims: B=8, T=1024, E=1024, H=16, HD=64, FF=4096, M = B*T = 8192

// ---------------- scratch (device globals; no allocations allowed) ----------
__device__ float g_qkv[(size_t)8192 * 3072];
__device__ float g_attn[(size_t)8192 * 1024];
__device__ float g_s[(size_t)8192 * 1024];
__device__ float g_x1[(size_t)8192 * 1024];
__device__ float g_ff[(size_t)8192 * 4096];
__device__ float g_wq[12582912];   // rounded weights: in_w 0, out_w 3145728, fc1_w 4194304, fc2_w 8388608
__device__ int   g_len[8];

// ---------------- padding-mask dtype detection + length extraction ----------
__global__ void mask_len_kernel(const void* mask) {
    __shared__ int sGT1, sEQ1, sF32;
    if (threadIdx.x == 0) { sGT1 = 0; sEQ1 = 0; sF32 = 0; }
    __syncthreads();
    const unsigned int* w = (const unsigned int*)mask;
    int gt1 = 0, eq1 = 0, f32 = 0;
    for (int i = threadIdx.x; i < 2048; i += 256) {
        unsigned int v = w[i];
        if (v == 0x3F800000u)      f32 = 1;
        else if (v == 1u)          eq1 = 1;
        else if (v != 0u)          gt1 = 1;
    }
    if (f32) atomicOr(&sF32, 1);
    if (gt1) atomicOr(&sGT1, 1);
    if (eq1) atomicOr(&sEQ1, 1);
    __syncthreads();
    if (threadIdx.x < 8) {
        const int b = threadIdx.x;
        int len = 1024;
        if (sF32) {
            const float* p = (const float*)mask;
            for (int k = 0; k < 1024; ++k)
                if (p[(size_t)b * 1024 + k] != 0.f) { len = k; break; }
        } else if (sGT1) {
            const unsigned char* p = (const unsigned char*)mask;
            for (int k = 0; k < 1024; ++k)
                if (p[(size_t)b * 1024 + k]) { len = k; break; }
        } else if (sEQ1) {
            const int* p = (const int*)mask;
            for (int k = 0; k < 1024; ++k)
                if (p[(size_t)b * 1024 + k]) { len = k; break; }
        }
        g_len[b] = len;
    }
}

// ---------------- common helpers -------------------------------------------
__device__ __forceinline__ uint32_t f2tf(float x) {
    uint32_t r;
    asm("cvt.rna.tf32.f32 %0, %1;" : "=r"(r) : "f"(x));
    return r;
}
__device__ __forceinline__ void mma_tf32(float* d, const uint32_t* a, const uint32_t* b) {
    asm volatile(
        "mma.sync.aligned.m16n8k8.row.col.f32.tf32.tf32.f32 "
        "{%0,%1,%2,%3}, {%4,%5,%6,%7}, {%8,%9}, {%0,%1,%2,%3};"
        : "+f"(d[0]), "+f"(d[1]), "+f"(d[2]), "+f"(d[3])
        : "r"(a[0]), "r"(a[1]), "r"(a[2]), "r"(a[3]), "r"(b[0]), "r"(b[1]));
}
__device__ __forceinline__ void ldsm4(uint32_t& r0, uint32_t& r1, uint32_t& r2, uint32_t& r3,
                                      uint32_t addr) {
    asm volatile("ldmatrix.sync.aligned.m8n8.x4.shared.b16 {%0,%1,%2,%3}, [%4];"
                 : "=r"(r0), "=r"(r1), "=r"(r2), "=r"(r3) : "r"(addr));
}
__device__ __forceinline__ uint32_t s2u(const void* p) {
    return (uint32_t)__cvta_generic_to_shared(p);
}
__device__ __forceinline__ void cpasync16(uint32_t dst, const void* src) {
    asm volatile("cp.async.cg.shared.global [%0], [%1], 16;"
                 :: "r"(dst), "l"(src) : "memory");
}

// ---------------- tf32 RNA pre-rounding pass (weights only) -----------------
__global__ __launch_bounds__(256) void cvt_tf32_kernel(
    const float* __restrict__ src, float* __restrict__ dst, int n4)
{
    int i = blockIdx.x * 256 + threadIdx.x;
    if (i < n4) {
        float4 v = ((const float4*)src)[i];
        float4 o;
        o.x = __uint_as_float(f2tf(v.x));
        o.y = __uint_as_float(f2tf(v.y));
        o.z = __uint_as_float(f2tf(v.z));
        o.w = __uint_as_float(f2tf(v.w));
        ((float4*)dst)[i] = o;
    }
}

// ---------------- tf32 tensor-core GEMM (64x64 warp tile) -------------------
// C[M,N] = A[M,K] @ W[N,K]^T + bias (+res/+relu).
// CTA tile 128x128, kstep 16, 128 threads = 4 warps (2m x 2n), warp tile
// 64x64 -> mma:ldsm ratio 4.0 (R7's 32x64 was 2.67; R8 showed the kernel is
// LDSM-issue bound, so raise work per shared-pipe issue).  2 CTAs/SM.
// SMEM: 4 stages x 16KB (A 8KB + B 8KB); chunk swizzle: 16B chunk c of row r
// at byte r*64 + 16*(c ^ ((r>>1)&3)).  Pipeline = R7: one barrier per k-tile,
// wait_group 2, prefetch kt+3, kk8=1 via address XOR 32.
template <int EPI, bool ROUND_OUT>  // EPI 0: +bias, 1: +bias+res, 2: +bias+relu
__global__ __launch_bounds__(128, 2) void tgemm_kernel(
    const float* __restrict__ A, const float* __restrict__ W,
    const float* __restrict__ bias, const float* __restrict__ R,
    float* __restrict__ C, int Ksz, int Nsz)
{
    extern __shared__ uint32_t smem[];   // 4 stages x 16KB = 64KB
    const uint32_t sbase = s2u(smem);

    const int tid  = threadIdx.x;
    const int lane = tid & 31;
    const int warp = tid >> 5;
    const int wm   = warp & 1;          // 2 m-tiles of 64
    const int wn   = warp >> 1;         // 2 n-tiles of 64
    const int m0   = blockIdx.y * 128;
    const int n0   = blockIdx.x * 128;

    // staging: 8 cp.async/thread/stage (A 512 chunks, B 512 chunks)
    const float* srcp[8];
    uint32_t     dsto[8];
#pragma unroll
    for (int i = 0; i < 8; ++i) {
        int idx = i * 128 + tid;
        if (idx < 512) {                 // A: 128 rows x 4 chunks
            int row = idx >> 2, c = idx & 3;
            srcp[i] = A + (size_t)(m0 + row) * Ksz + c * 4;
            dsto[i] = row * 64 + 16 * (c ^ ((row >> 1) & 3));
        } else {                         // B: 128 rows x 4 chunks
            int j = idx - 512;
            int row = j >> 2, c = j & 3;
            srcp[i] = W + (size_t)(n0 + row) * Ksz + c * 4;
            dsto[i] = 8192 + row * 64 + 16 * (c ^ ((row >> 1) & 3));
        }
    }

    // fragment ldmatrix base addresses (stage 0, kk8=0); +1024B per 16 rows
    const int mat = lane >> 3, rr = lane & 7;
    const int ar  = wm * 64 + (mat & 1) * 8 + rr;
    const int cbA = mat >> 1;
    const uint32_t aA = sbase + ar * 64 + 16 * (cbA ^ ((ar >> 1) & 3));
    const int br  = wn * 64 + (mat >> 1) * 8 + rr;
    const int cbB = mat & 1;
    const uint32_t aB = sbase + 8192 + br * 64 + 16 * (cbB ^ ((br >> 1) & 3));

    float acc[4][8][4];                  // [m 16-tile][n 8-atom][frag]
#pragma unroll
    for (int i = 0; i < 4; ++i)
#pragma unroll
        for (int j = 0; j < 8; ++j)
#pragma unroll
            for (int r = 0; r < 4; ++r) acc[i][j][r] = 0.f;

    const int KT = Ksz >> 4;             // k-steps of 16

    // prologue: stages 0..2
#pragma unroll
    for (int p = 0; p < 3; ++p) {
        const uint32_t st = p * 16384;
#pragma unroll
        for (int i = 0; i < 8; ++i)
            cpasync16(sbase + st + dsto[i], srcp[i] + p * 16);
        asm volatile("cp.async.commit_group;" ::: "memory");
    }

    for (int kt = 0; kt < KT; ++kt) {
        asm volatile("cp.async.wait_group 2;" ::: "memory");
        __syncthreads();

        if (kt + 3 < KT) {
            const uint32_t st = ((kt + 3) & 3) * 16384;
#pragma unroll
            for (int i = 0; i < 8; ++i)
                cpasync16(sbase + st + dsto[i], srcp[i] + (kt + 3) * 16);
        }
        asm volatile("cp.async.commit_group;" ::: "memory");

        const uint32_t off = (kt & 3) * 16384;
        const uint32_t aAb = aA + off;
        const uint32_t aBb = aB + off;
#pragma unroll
        for (int kk8 = 0; kk8 < 2; ++kk8) {
            const uint32_t xo = kk8 << 5;        // kk=8 -> XOR 32 bytes
            uint32_t af[4][4];
#pragma unroll
            for (int i = 0; i < 4; ++i)
                ldsm4(af[i][0], af[i][1], af[i][2], af[i][3],
                      (aAb + i * 1024) ^ xo);
#pragma unroll
            for (int jp = 0; jp < 4; ++jp) {
                uint32_t bf[4];
                ldsm4(bf[0], bf[1], bf[2], bf[3], (aBb + jp * 1024) ^ xo);
#pragma unroll
                for (int i = 0; i < 4; ++i) {
                    mma_tf32(acc[i][2 * jp],     af[i], &bf[0]);
                    mma_tf32(acc[i][2 * jp + 1], af[i], &bf[2]);
                }
            }
        }
    }

    // epilogue
#pragma unroll
    for (int i = 0; i < 4; ++i) {
        int row = m0 + wm * 64 + i * 16 + (lane >> 2);
#pragma unroll
        for (int j = 0; j < 8; ++j) {
            int col = n0 + wn * 64 + j * 8 + (lane & 3) * 2;
            float b0v = bias[col], b1v = bias[col + 1];
            size_t o0 = (size_t)row * Nsz + col;
            size_t o1 = (size_t)(row + 8) * Nsz + col;
            float v0 = acc[i][j][0] + b0v, v1 = acc[i][j][1] + b1v;
            float v2 = acc[i][j][2] + b0v, v3 = acc[i][j][3] + b1v;
            if (EPI == 1) {
                v0 += R[o0]; v1 += R[o0 + 1];
                v2 += R[o1]; v3 += R[o1 + 1];
            }
            if (EPI == 2) {
                v0 = fmaxf(v0, 0.f); v1 = fmaxf(v1, 0.f);
                v2 = fmaxf(v2, 0.f); v3 = fmaxf(v3, 0.f);
            }
            if (ROUND_OUT) {
                v0 = __uint_as_float(f2tf(v0)); v1 = __uint_as_float(f2tf(v1));
                v2 = __uint_as_float(f2tf(v2)); v3 = __uint_as_float(f2tf(v3));
            }
            float2 q0v = { v0, v1 }, q1v = { v2, v3 };
            *(float2*)&C[o0] = q0v;
            *(float2*)&C[o1] = q1v;
        }
    }
}

// ---------------- attention: tf32-mma flash, per (b, h, 64-query tile) ------
__device__ __forceinline__ uint32_t aswz(uint32_t base, int row, int chunk) {
    int pos = (chunk & 8) | ((chunk & 7) ^ (row & 7));
    return base + (row * 64 + 4 * pos) * 4;
}

__global__ __launch_bounds__(128) void attn_kernel(
    const float* __restrict__ qkv, const int* __restrict__ lenv,
    float* __restrict__ out)
{
    __shared__ uint32_t Qs[64 * 64];
    __shared__ uint32_t KP[64 * 64];
    __shared__ uint32_t Vt[64 * 64];

    const int tid  = threadIdx.x;
    const int lane = tid & 31;
    const int wrp  = tid >> 5;
    const int b    = blockIdx.z;
    const int h    = blockIdx.y;
    const int qt   = blockIdx.x;
    const int q0   = qt * 64;
    const int blen = lenv[b];
    const float scale = 0.125f;

    const uint32_t Qb = s2u(Qs), Kb = s2u(KP), Vb = s2u(Vt);

    for (int i = tid; i < 64 * 16; i += 128) {
        int r = i >> 4, c4 = i & 15;
        float4 v = *(const float4*)&qkv[(size_t)(b * 1024 + q0 + r) * 3072 + h * 64 + c4 * 4];
        int pos = (c4 & 8) | ((c4 & 7) ^ (r & 7));
        uint32_t t[4] = { f2tf(v.x * scale), f2tf(v.y * scale),
                          f2tf(v.z * scale), f2tf(v.w * scale) };
        *(uint4*)&Qs[r * 64 + 4 * pos] = *(uint4*)t;
    }

    const int mat = lane >> 3, rr = lane & 7;
    const int g   = lane >> 2;
    const int q2  = lane & 3;
    const int aRowQ = wrp * 16 + (mat & 1) * 8 + rr;
    const int cbitA = mat >> 1;
    const int cbitB = mat & 1;
    const int bRowOff = (mat >> 1) * 8 + rr;

    float O[8][4];
    float m0r = -1e30f, m1r = -1e30f, l0r = 0.f, l1r = 0.f;
#pragma unroll
    for (int j = 0; j < 8; ++j)
#pragma unroll
        for (int r = 0; r < 4; ++r) O[j][r] = 0.f;

    const int ktmax = qt;
    for (int kt = 0; kt <= ktmax && kt * 64 < blen; ++kt) {
        const int k0 = kt * 64;
        __syncthreads();

        for (int i = tid; i < 64 * 16; i += 128) {
            int r = i >> 4, c4 = i & 15;
            float4 v = *(const float4*)&qkv[(size_t)(b * 1024 + k0 + r) * 3072 + 1024 + h * 64 + c4 * 4];
            int pos = (c4 & 8) | ((c4 & 7) ^ (r & 7));
            uint32_t t[4] = { f2tf(v.x), f2tf(v.y), f2tf(v.z), f2tf(v.w) };
            *(uint4*)&KP[r * 64 + 4 * pos] = *(uint4*)t;
        }
        for (int i = tid; i < 64 * 16; i += 128) {
            int key = i & 63, dc = i >> 6;
            float4 v = *(const float4*)&qkv[(size_t)(b * 1024 + k0 + key) * 3072 + 2048 + h * 64 + dc * 4];
            int kc = key >> 2, kb = key & 3;
            float e[4] = { v.x, v.y, v.z, v.w };
#pragma unroll
            for (int s = 0; s < 4; ++s) {
                int d = dc * 4 + s;
                int pos = (kc & 8) | ((kc & 7) ^ (d & 7));
                Vt[d * 64 + 4 * pos + kb] = f2tf(e[s]);
            }
        }
        __syncthreads();

        float s[8][4];
#pragma unroll
        for (int j = 0; j < 8; ++j)
#pragma unroll
            for (int r = 0; r < 4; ++r) s[j][r] = 0.f;

#pragma unroll
        for (int kk = 0; kk < 8; ++kk) {
            int ck = kk * 2;
            uint32_t af[4];
            ldsm4(af[0], af[1], af[2], af[3], aswz(Qb, aRowQ, ck + cbitA));
#pragma unroll
            for (int jp = 0; jp < 4; ++jp) {
                uint32_t bf[4];
                ldsm4(bf[0], bf[1], bf[2], bf[3],
                      aswz(Kb, jp * 16 + bRowOff, ck + cbitB));
                mma_tf32(s[2 * jp],     af, &bf[0]);
                mma_tf32(s[2 * jp + 1], af, &bf[2]);
            }
        }

        const int qr0 = q0 + wrp * 16 + g;
        const int qr1 = qr0 + 8;
#pragma unroll
        for (int j = 0; j < 8; ++j) {
            int c0 = k0 + j * 8 + q2 * 2;
            int c1 = c0 + 1;
            if (c0 > qr0 || c0 >= blen) s[j][0] = -1e30f;
            if (c1 > qr0 || c1 >= blen) s[j][1] = -1e30f;
            if (c0 > qr1 || c0 >= blen) s[j][2] = -1e30f;
            if (c1 > qr1 || c1 >= blen) s[j][3] = -1e30f;
        }
        float mx0 = -1e30f, mx1 = -1e30f;
#pragma unroll
        for (int j = 0; j < 8; ++j) {
            mx0 = fmaxf(mx0, fmaxf(s[j][0], s[j][1]));
            mx1 = fmaxf(mx1, fmaxf(s[j][2], s[j][3]));
        }
        mx0 = fmaxf(mx0, __shfl_xor_sync(0xffffffffu, mx0, 1));
        mx0 = fmaxf(mx0, __shfl_xor_sync(0xffffffffu, mx0, 2));
        mx1 = fmaxf(mx1, __shfl_xor_sync(0xffffffffu, mx1, 1));
        mx1 = fmaxf(mx1, __shfl_xor_sync(0xffffffffu, mx1, 2));
        float mn0 = fmaxf(m0r, mx0), mn1 = fmaxf(m1r, mx1);
        float al0 = __expf(m0r - mn0), al1 = __expf(m1r - mn1);
        float sm0 = 0.f, sm1 = 0.f;
#pragma unroll
        for (int j = 0; j < 8; ++j) {
            s[j][0] = __expf(s[j][0] - mn0);
            s[j][1] = __expf(s[j][1] - mn0);
            s[j][2] = __expf(s[j][2] - mn1);
            s[j][3] = __expf(s[j][3] - mn1);
            sm0 += s[j][0] + s[j][1];
            sm1 += s[j][2] + s[j][3];
        }
        sm0 += __shfl_xor_sync(0xffffffffu, sm0, 1);
        sm0 += __shfl_xor_sync(0xffffffffu, sm0, 2);
        sm1 += __shfl_xor_sync(0xffffffffu, sm1, 1);
        sm1 += __shfl_xor_sync(0xffffffffu, sm1, 2);
        l0r = l0r * al0 + sm0;
        l1r = l1r * al1 + sm1;
        m0r = mn0; m1r = mn1;
#pragma unroll
        for (int j = 0; j < 8; ++j) {
            O[j][0] *= al0; O[j][1] *= al0;
            O[j][2] *= al1; O[j][3] *= al1;
        }

        __syncthreads();
#pragma unroll
        for (int j = 0; j < 8; ++j) {
            int key = j * 8 + q2 * 2;
            int kc  = key >> 2;
            int pos = (kc & 8) | ((kc & 7) ^ (g & 7));
            int wrd = (wrp * 16 + g) * 64 + 4 * pos + (key & 3);
            uint32_t p0[2] = { f2tf(s[j][0]), f2tf(s[j][1]) };
            *(uint2*)&KP[wrd] = *(uint2*)p0;
            uint32_t p1[2] = { f2tf(s[j][2]), f2tf(s[j][3]) };
            *(uint2*)&KP[wrd + 8 * 64] = *(uint2*)p1;
        }
        __syncthreads();

#pragma unroll
        for (int kk = 0; kk < 8; ++kk) {
            int ck = kk * 2;
            uint32_t af[4];
            ldsm4(af[0], af[1], af[2], af[3], aswz(Kb, aRowQ, ck + cbitA));
#pragma unroll
            for (int jp = 0; jp < 4; ++jp) {
                uint32_t bf[4];
                ldsm4(bf[0], bf[1], bf[2], bf[3],
                      aswz(Vb, jp * 16 + bRowOff, ck + cbitB));
                mma_tf32(O[2 * jp],     af, &bf[0]);
                mma_tf32(O[2 * jp + 1], af, &bf[2]);
            }
        }
    }

    // epilogue: normalize, round to tf32 (feeds the out-proj GEMM exactly)
    const float inv0 = 1.f / l0r, inv1 = 1.f / l1r;
    const int row0 = b * 1024 + q0 + wrp * 16 + g;
#pragma unroll
    for (int j = 0; j < 8; ++j) {
        int d = h * 64 + j * 8 + q2 * 2;
        float2 v0 = { __uint_as_float(f2tf(O[j][0] * inv0)),
                      __uint_as_float(f2tf(O[j][1] * inv0)) };
        float2 v1 = { __uint_as_float(f2tf(O[j][2] * inv1)),
                      __uint_as_float(f2tf(O[j][3] * inv1)) };
        *(float2*)&out[(size_t)row0 * 1024 + d] = v0;
        *(float2*)&out[(size_t)(row0 + 8) * 1024 + d] = v1;
    }
}

// ---------------- LayerNorm ------------------------------------------------
__global__ __launch_bounds__(256) void ln_kernel(
    const float* __restrict__ X, const float* __restrict__ w,
    const float* __restrict__ bb, float* __restrict__ Y)
{
    const int row = blockIdx.x;
    const int t   = threadIdx.x;
    float4 x = *(const float4*)&X[(size_t)row * 1024 + t * 4];
    float s = x.x + x.y + x.z + x.w;
    float q = fmaf(x.x, x.x, fmaf(x.y, x.y, fmaf(x.z, x.z, x.w * x.w)));
#pragma unroll
    for (int off = 16; off; off >>= 1) {
        s += __shfl_xor_sync(0xffffffffu, s, off);
        q += __shfl_xor_sync(0xffffffffu, q, off);
    }
    __shared__ float ss[8], qq[8];
    const int warp = t >> 5, lane = t & 31;
    if (lane == 0) { ss[warp] = s; qq[warp] = q; }
    __syncthreads();
    float S = 0.f, Q2 = 0.f;
#pragma unroll
    for (int i = 0; i < 8; ++i) { S += ss[i]; Q2 += qq[i]; }
    const float mean = S * (1.0f / 1024.0f);
    const float var  = fmaxf(Q2 * (1.0f / 1024.0f) - mean * mean, 0.f);
    const float inv  = rsqrtf(var + 1e-12f);
    float4 wv = *(const float4*)&w[t * 4];
    float4 bv = *(const float4*)&bb[t * 4];
    float4 y;
    y.x = wv.x * (x.x - mean) * inv + bv.x;
    y.y = wv.y * (x.y - mean) * inv + bv.y;
    y.z = wv.z * (x.z - mean) * inv + bv.z;
    y.w = wv.w * (x.w - mean) * inv + bv.w;
    *(float4*)&Y[(size_t)row * 1024 + t * 4] = y;
}

// ---------------- launch ----------------------------------------------------
static constexpr int TG_SMEM = 65536;   // 4 stages x 16KB

extern "C" void kernel_launch(void* const* d_in, const int* in_sizes, int n_in,
                              void* d_out, int out_size)
{
    const float* x     = (const float*)d_in[0];
    const float* in_w  = (const float*)d_in[1];
    const float* in_b  = (const float*)d_in[2];
    const float* out_w = (const float*)d_in[3];
    const float* out_b = (const float*)d_in[4];
    const float* fc1_w = (const float*)d_in[5];
    const float* fc1_b = (const float*)d_in[6];
    const float* fc2_w = (const float*)d_in[7];
    const float* fc2_b = (const float*)d_in[8];
    const float* ln1_w = (const float*)d_in[9];
    const float* ln1_b = (const float*)d_in[10];
    const float* ln2_w = (const float*)d_in[11];
    const float* ln2_b = (const float*)d_in[12];
    const void*  pad   = d_in[13];
    float* out = (float*)d_out;

    float *qkv, *attn, *sbuf, *x1, *ff, *wq;
    int* lenv;
    cudaGetSymbolAddress((void**)&qkv,  g_qkv);
    cudaGetSymbolAddress((void**)&attn, g_attn);
    cudaGetSymbolAddress((void**)&sbuf, g_s);
    cudaGetSymbolAddress((void**)&x1,   g_x1);
    cudaGetSymbolAddress((void**)&ff,   g_ff);
    cudaGetSymbolAddress((void**)&wq,   g_wq);
    cudaGetSymbolAddress((void**)&lenv, g_len);

    float* w_in  = wq;
    float* w_out = wq + 3145728;
    float* w_f1  = wq + 4194304;
    float* w_f2  = wq + 8388608;

    static bool attr_done = false;
    if (!attr_done) {
        cudaFuncSetAttribute(tgemm_kernel<0, false>, cudaFuncAttributeMaxDynamicSharedMemorySize, TG_SMEM);
        cudaFuncSetAttribute(tgemm_kernel<1, false>, cudaFuncAttributeMaxDynamicSharedMemorySize, TG_SMEM);
        cudaFuncSetAttribute(tgemm_kernel<2, true>,  cudaFuncAttributeMaxDynamicSharedMemorySize, TG_SMEM);
        attr_done = true;
    }

    mask_len_kernel<<<1, 256>>>(pad);
    // pre-round weights to tf32 (RNA); activations rounded by producing kernels
    cvt_tf32_kernel<<<3072, 256>>>(in_w,  w_in,   786432);
    cvt_tf32_kernel<<<1024, 256>>>(out_w, w_out,  262144);
    cvt_tf32_kernel<<<4096, 256>>>(fc1_w, w_f1,  1048576);
    cvt_tf32_kernel<<<4096, 256>>>(fc2_w, w_f2,  1048576);

    // 1) qkv = x @ in_w^T + in_b           [8192, 3072]
    tgemm_kernel<0, false><<<dim3(24, 64), 128, TG_SMEM>>>(x, w_in, in_b, nullptr, qkv, 1024, 3072);
    // 2) attention -> attn (tf32-rounded)  [8192, 1024]
    attn_kernel<<<dim3(16, 16, 8), 128>>>(qkv, lenv, attn);
    // 3) s1 = attn @ out_w^T + out_b + x   [8192, 1024]  (both operands exact tf32)
    tgemm_kernel<1, false><<<dim3(8, 64), 128, TG_SMEM>>>(attn, w_out, out_b, x, sbuf, 1024, 1024);
    // 4) x1 = LN1(s1)
    ln_kernel<<<8192, 256>>>(sbuf, ln1_w, ln1_b, x1);
    // 5) ff = relu(x1 @ fc1_w^T + fc1_b) (tf32-rounded)  [8192, 4096]
    tgemm_kernel<2, true><<<dim3(32, 64), 128, TG_SMEM>>>(x1, w_f1, fc1_b, nullptr, ff, 1024, 4096);
    // 6) s2 = ff @ fc2_w^T + fc2_b + x1    [8192, 1024]  (both operands exact tf32)
    tgemm_kernel<1, false><<<dim3(8, 64), 128, TG_SMEM>>>(ff, w_f2, fc2_b, x1, sbuf, 4096, 1024);
    // 7) out = LN2(s2)
    ln_kernel<<<8192, 256>>>(sbuf, ln2_w, ln2_b, out);
}

// round 12
// speedup vs baseline: 1.3202x; 1.0702x over previous
#include <cuda_runtime.h>
#include <math.h>
#include <stdint.h>

// Problem dims: B=8, T=1024, E=1024, H=16, HD=64, FF=4096, M = B*T = 8192

// ---------------- scratch (device globals; no allocations allowed) ----------
__device__ float g_qkv[(size_t)8192 * 3072];
__device__ float g_attn[(size_t)8192 * 1024];
__device__ float g_s[(size_t)8192 * 1024];
__device__ float g_x1[(size_t)8192 * 1024];
__device__ float g_ff[(size_t)8192 * 4096];
__device__ float g_wq[12582912];   // rounded weights: in_w 0, out_w 3145728, fc1_w 4194304, fc2_w 8388608
__device__ int   g_len[8];

// ---------------- padding-mask: dtype detect + PARALLEL length extraction ---
// (The old version had 8 threads doing serial early-break scans of ~700
//  stride-4KB loads each — a hidden latency chain on one block.)
__global__ void mask_len_kernel(const void* mask) {
    __shared__ int flags[3];           // 0: f32, 1: gt1 (u8), 2: eq1 (i32)
    __shared__ int lensh[8];
    const int tid = threadIdx.x;
    if (tid < 3) flags[tid] = 0;
    if (tid < 8) lensh[tid] = 1024;
    __syncthreads();

    const unsigned int* w = (const unsigned int*)mask;
    int f32 = 0, gt1 = 0, eq1 = 0;
    for (int i = tid; i < 2048; i += 256) {
        unsigned int v = w[i];
        if (v == 0x3F800000u)      f32 = 1;
        else if (v == 1u)          eq1 = 1;
        else if (v != 0u)          gt1 = 1;
    }
    if (f32) atomicOr(&flags[0], 1);
    if (gt1) atomicOr(&flags[1], 1);
    if (eq1) atomicOr(&flags[2], 1);
    __syncthreads();

    if (flags[0]) {                    // float32 bool
        const float* p = (const float*)mask;
        for (int i = tid; i < 8192; i += 256)
            if (p[i] != 0.f) atomicMin(&lensh[i >> 10], i & 1023);
    } else if (flags[1]) {             // uint8 bool
        const unsigned char* p = (const unsigned char*)mask;
        for (int i = tid; i < 8192; i += 256)
            if (p[i]) atomicMin(&lensh[i >> 10], i & 1023);
    } else if (flags[2]) {             // int32 bool
        const int* p = (const int*)mask;
        for (int i = tid; i < 8192; i += 256)
            if (p[i]) atomicMin(&lensh[i >> 10], i & 1023);
    }
    __syncthreads();
    if (tid < 8) g_len[tid] = lensh[tid];
}

// ---------------- common helpers -------------------------------------------
__device__ __forceinline__ uint32_t f2tf(float x) {
    uint32_t r;
    asm("cvt.rna.tf32.f32 %0, %1;" : "=r"(r) : "f"(x));
    return r;
}
__device__ __forceinline__ void mma_tf32(float* d, const uint32_t* a, const uint32_t* b) {
    asm volatile(
        "mma.sync.aligned.m16n8k8.row.col.f32.tf32.tf32.f32 "
        "{%0,%1,%2,%3}, {%4,%5,%6,%7}, {%8,%9}, {%0,%1,%2,%3};"
        : "+f"(d[0]), "+f"(d[1]), "+f"(d[2]), "+f"(d[3])
        : "r"(a[0]), "r"(a[1]), "r"(a[2]), "r"(a[3]), "r"(b[0]), "r"(b[1]));
}
__device__ __forceinline__ void ldsm4(uint32_t& r0, uint32_t& r1, uint32_t& r2, uint32_t& r3,
                                      uint32_t addr) {
    asm volatile("ldmatrix.sync.aligned.m8n8.x4.shared.b16 {%0,%1,%2,%3}, [%4];"
                 : "=r"(r0), "=r"(r1), "=r"(r2), "=r"(r3) : "r"(addr));
}
__device__ __forceinline__ uint32_t s2u(const void* p) {
    return (uint32_t)__cvta_generic_to_shared(p);
}
__device__ __forceinline__ void cpasync16(uint32_t dst, const void* src) {
    asm volatile("cp.async.cg.shared.global [%0], [%1], 16;"
                 :: "r"(dst), "l"(src) : "memory");
}

// ---------------- merged tf32 RNA weight-rounding pass ----------------------
// One launch rounds all 4 weight matrices into g_wq.
__global__ __launch_bounds__(256) void cvt_all_kernel(
    const float* __restrict__ in_w, const float* __restrict__ out_w,
    const float* __restrict__ fc1_w, const float* __restrict__ fc2_w,
    float* __restrict__ wq)
{
    int i = blockIdx.x * 256 + threadIdx.x;     // float4 index, < 3145728
    const float4* src;
    float4* dst;
    if (i < 786432) {
        src = (const float4*)in_w + i;           dst = (float4*)wq + i;
    } else if (i < 1048576) {
        int j = i - 786432;
        src = (const float4*)out_w + j;          dst = (float4*)(wq + 3145728) + j;
    } else if (i < 2097152) {
        int j = i - 1048576;
        src = (const float4*)fc1_w + j;          dst = (float4*)(wq + 4194304) + j;
    } else {
        int j = i - 2097152;
        src = (const float4*)fc2_w + j;          dst = (float4*)(wq + 8388608) + j;
    }
    float4 v = *src;
    float4 o;
    o.x = __uint_as_float(f2tf(v.x));
    o.y = __uint_as_float(f2tf(v.y));
    o.z = __uint_as_float(f2tf(v.z));
    o.w = __uint_as_float(f2tf(v.w));
    *dst = o;
}

// ---------------- tf32 tensor-core GEMM (R7 config, proven fastest) ---------
// C[M,N] = A[M,K] @ W[N,K]^T + bias (+res/+relu).
// 128x128 tile, kstep 16, 8 warps (4m x 2n), warp tile 32x64, 2 CTAs/SM.
// Raw fp32 staged by cp.async; HMMA truncates to tf32 (RZ).  Weights are
// pre-rounded RNA in GMEM so the W side is exact.
// SMEM tile [row][16 words], chunk swizzle: 16B chunk c of row r at word
// r*16 + 4*(c ^ ((r>>1)&3)).  4 stages x 16KB, wait_group 2, prefetch kt+3.
template <int EPI, bool ROUND_OUT>  // EPI 0: +bias, 1: +bias+res, 2: +bias+relu
__global__ __launch_bounds__(256, 2) void tgemm_kernel(
    const float* __restrict__ A, const float* __restrict__ W,
    const float* __restrict__ bias, const float* __restrict__ R,
    float* __restrict__ C, int Ksz, int Nsz)
{
    extern __shared__ uint32_t smem[];   // 4 stages x 16KB = 64KB
    const uint32_t sbase = s2u(smem);

    const int tid  = threadIdx.x;
    const int lane = tid & 31;
    const int warp = tid >> 5;
    const int wm   = warp & 3;
    const int wn   = warp >> 2;
    const int m0   = blockIdx.y * 128;
    const int n0   = blockIdx.x * 128;

    // staging map: rows sr, sr+64, 16B chunk sc, for both A and B
    const int sr = tid >> 2;             // 0..63
    const int sc = tid & 3;
    const uint32_t swz = 4 * (sc ^ ((sr >> 1) & 3));
    const uint32_t dA0 = (sr * 16 + swz) * 4;
    const uint32_t dA1 = ((sr + 64) * 16 + swz) * 4;

    const float* Ap0 = A + (size_t)(m0 + sr) * Ksz + sc * 4;
    const float* Ap1 = A + (size_t)(m0 + sr + 64) * Ksz + sc * 4;
    const float* Wp0 = W + (size_t)(n0 + sr) * Ksz + sc * 4;
    const float* Wp1 = W + (size_t)(n0 + sr + 64) * Ksz + sc * 4;

    // fragment ldmatrix base offsets (stage 0)
    const int mat = lane >> 3, rr = lane & 7;
    const int ar  = wm * 32 + (mat & 1) * 8 + rr;
    const int ac  = mat >> 1;
    const uint32_t aA = sbase + (ar * 16 + 4 * (ac ^ ((ar >> 1) & 3))) * 4;
    const int br  = wn * 64 + (mat >> 1) * 8 + rr;
    const int bc  = mat & 1;
    const uint32_t aB = sbase + 8192 + (br * 16 + 4 * (bc ^ ((br >> 1) & 3))) * 4;

    float acc[2][8][4];
#pragma unroll
    for (int i = 0; i < 2; ++i)
#pragma unroll
        for (int j = 0; j < 8; ++j)
#pragma unroll
            for (int r = 0; r < 4; ++r) acc[i][j][r] = 0.f;

    const int KT = Ksz >> 4;             // k-steps of 16

    // prologue: stages 0..2
#pragma unroll
    for (int p = 0; p < 3; ++p) {
        const uint32_t st = sbase + p * 16384;
        cpasync16(st + dA0,        Ap0 + p * 16);
        cpasync16(st + dA1,        Ap1 + p * 16);
        cpasync16(st + 8192 + dA0, Wp0 + p * 16);
        cpasync16(st + 8192 + dA1, Wp1 + p * 16);
        asm volatile("cp.async.commit_group;" ::: "memory");
    }

    for (int kt = 0; kt < KT; ++kt) {
        asm volatile("cp.async.wait_group 2;" ::: "memory");
        __syncthreads();

        if (kt + 3 < KT) {
            const uint32_t st = sbase + ((kt + 3) & 3) * 16384;
            cpasync16(st + dA0,        Ap0 + (kt + 3) * 16);
            cpasync16(st + dA1,        Ap1 + (kt + 3) * 16);
            cpasync16(st + 8192 + dA0, Wp0 + (kt + 3) * 16);
            cpasync16(st + 8192 + dA1, Wp1 + (kt + 3) * 16);
        }
        asm volatile("cp.async.commit_group;" ::: "memory");

        const uint32_t off = (kt & 3) * 16384;
        const uint32_t aAb = aA + off;
        const uint32_t aBb = aB + off;
#pragma unroll
        for (int kk8 = 0; kk8 < 2; ++kk8) {
            const uint32_t xo = kk8 << 5;        // kk=8 -> XOR 32 bytes
            uint32_t af0[4], af1[4];
            ldsm4(af0[0], af0[1], af0[2], af0[3], aAb ^ xo);
            ldsm4(af1[0], af1[1], af1[2], af1[3], (aAb + 1024) ^ xo);
#pragma unroll
            for (int jp = 0; jp < 4; ++jp) {
                uint32_t bf[4];
                ldsm4(bf[0], bf[1], bf[2], bf[3], (aBb + jp * 1024) ^ xo);
                mma_tf32(acc[0][2 * jp],     af0, &bf[0]);
                mma_tf32(acc[1][2 * jp],     af1, &bf[0]);
                mma_tf32(acc[0][2 * jp + 1], af0, &bf[2]);
                mma_tf32(acc[1][2 * jp + 1], af1, &bf[2]);
            }
        }
    }

    // epilogue
#pragma unroll
    for (int i = 0; i < 2; ++i) {
        int row = m0 + wm * 32 + i * 16 + (lane >> 2);
#pragma unroll
        for (int j = 0; j < 8; ++j) {
            int col = n0 + wn * 64 + j * 8 + (lane & 3) * 2;
            float b0v = bias[col], b1v = bias[col + 1];
            size_t o0 = (size_t)row * Nsz + col;
            size_t o1 = (size_t)(row + 8) * Nsz + col;
            float v0 = acc[i][j][0] + b0v, v1 = acc[i][j][1] + b1v;
            float v2 = acc[i][j][2] + b0v, v3 = acc[i][j][3] + b1v;
            if (EPI == 1) {
                v0 += R[o0]; v1 += R[o0 + 1];
                v2 += R[o1]; v3 += R[o1 + 1];
            }
            if (EPI == 2) {
                v0 = fmaxf(v0, 0.f); v1 = fmaxf(v1, 0.f);
                v2 = fmaxf(v2, 0.f); v3 = fmaxf(v3, 0.f);
            }
            if (ROUND_OUT) {
                v0 = __uint_as_float(f2tf(v0)); v1 = __uint_as_float(f2tf(v1));
                v2 = __uint_as_float(f2tf(v2)); v3 = __uint_as_float(f2tf(v3));
            }
            float2 q0v = { v0, v1 }, q1v = { v2, v3 };
            *(float2*)&C[o0] = q0v;
            *(float2*)&C[o1] = q1v;
        }
    }
}

// ---------------- attention: tf32-mma flash, per (b, h, 64-query tile) ------
// Raw fp32 staging (HMMA RZ-truncates); RNA rounding only at the epilogue so
// the out-proj GEMM sees exact tf32 operands.
__device__ __forceinline__ uint32_t aswz(uint32_t base, int row, int chunk) {
    int pos = (chunk & 8) | ((chunk & 7) ^ (row & 7));
    return base + (row * 64 + 4 * pos) * 4;
}

__global__ __launch_bounds__(128) void attn_kernel(
    const float* __restrict__ qkv, const int* __restrict__ lenv,
    float* __restrict__ out)
{
    __shared__ uint32_t Qs[64 * 64];
    __shared__ uint32_t KP[64 * 64];
    __shared__ uint32_t Vt[64 * 64];

    const int tid  = threadIdx.x;
    const int lane = tid & 31;
    const int wrp  = tid >> 5;
    const int b    = blockIdx.z;
    const int h    = blockIdx.y;
    const int qt   = blockIdx.x;
    const int q0   = qt * 64;
    const int blen = lenv[b];
    const float scale = 0.125f;

    const uint32_t Qb = s2u(Qs), Kb = s2u(KP), Vb = s2u(Vt);

    for (int i = tid; i < 64 * 16; i += 128) {
        int r = i >> 4, c4 = i & 15;
        float4 v = *(const float4*)&qkv[(size_t)(b * 1024 + q0 + r) * 3072 + h * 64 + c4 * 4];
        int pos = (c4 & 8) | ((c4 & 7) ^ (r & 7));
        uint32_t t[4] = { __float_as_uint(v.x * scale), __float_as_uint(v.y * scale),
                          __float_as_uint(v.z * scale), __float_as_uint(v.w * scale) };
        *(uint4*)&Qs[r * 64 + 4 * pos] = *(uint4*)t;
    }

    const int mat = lane >> 3, rr = lane & 7;
    const int g   = lane >> 2;
    const int q2  = lane & 3;
    const int aRowQ = wrp * 16 + (mat & 1) * 8 + rr;
    const int cbitA = mat >> 1;
    const int cbitB = mat & 1;
    const int bRowOff = (mat >> 1) * 8 + rr;

    float O[8][4];
    float m0r = -1e30f, m1r = -1e30f, l0r = 0.f, l1r = 0.f;
#pragma unroll
    for (int j = 0; j < 8; ++j)
#pragma unroll
        for (int r = 0; r < 4; ++r) O[j][r] = 0.f;

    const int ktmax = qt;
    for (int kt = 0; kt <= ktmax && kt * 64 < blen; ++kt) {
        const int k0 = kt * 64;
        __syncthreads();

        for (int i = tid; i < 64 * 16; i += 128) {
            int r = i >> 4, c4 = i & 15;
            float4 v = *(const float4*)&qkv[(size_t)(b * 1024 + k0 + r) * 3072 + 1024 + h * 64 + c4 * 4];
            int pos = (c4 & 8) | ((c4 & 7) ^ (r & 7));
            uint32_t t[4] = { __float_as_uint(v.x), __float_as_uint(v.y),
                              __float_as_uint(v.z), __float_as_uint(v.w) };
            *(uint4*)&KP[r * 64 + 4 * pos] = *(uint4*)t;
        }
        for (int i = tid; i < 64 * 16; i += 128) {
            int key = i & 63, dc = i >> 6;
            float4 v = *(const float4*)&qkv[(size_t)(b * 1024 + k0 + key) * 3072 + 2048 + h * 64 + dc * 4];
            int kc = key >> 2, kb = key & 3;
            float e[4] = { v.x, v.y, v.z, v.w };
#pragma unroll
            for (int s = 0; s < 4; ++s) {
                int d = dc * 4 + s;
                int pos = (kc & 8) | ((kc & 7) ^ (d & 7));
                Vt[d * 64 + 4 * pos + kb] = __float_as_uint(e[s]);
            }
        }
        __syncthreads();

        float s[8][4];
#pragma unroll
        for (int j = 0; j < 8; ++j)
#pragma unroll
            for (int r = 0; r < 4; ++r) s[j][r] = 0.f;

#pragma unroll
        for (int kk = 0; kk < 8; ++kk) {
            int ck = kk * 2;
            uint32_t af[4];
            ldsm4(af[0], af[1], af[2], af[3], aswz(Qb, aRowQ, ck + cbitA));
#pragma unroll
            for (int jp = 0; jp < 4; ++jp) {
                uint32_t bf[4];
                ldsm4(bf[0], bf[1], bf[2], bf[3],
                      aswz(Kb, jp * 16 + bRowOff, ck + cbitB));
                mma_tf32(s[2 * jp],     af, &bf[0]);
                mma_tf32(s[2 * jp + 1], af, &bf[2]);
            }
        }

        const int qr0 = q0 + wrp * 16 + g;
        const int qr1 = qr0 + 8;
#pragma unroll
        for (int j = 0; j < 8; ++j) {
            int c0 = k0 + j * 8 + q2 * 2;
            int c1 = c0 + 1;
            if (c0 > qr0 || c0 >= blen) s[j][0] = -1e30f;
            if (c1 > qr0 || c1 >= blen) s[j][1] = -1e30f;
            if (c0 > qr1 || c0 >= blen) s[j][2] = -1e30f;
            if (c1 > qr1 || c1 >= blen) s[j][3] = -1e30f;
        }
        float mx0 = -1e30f, mx1 = -1e30f;
#pragma unroll
        for (int j = 0; j < 8; ++j) {
            mx0 = fmaxf(mx0, fmaxf(s[j][0], s[j][1]));
            mx1 = fmaxf(mx1, fmaxf(s[j][2], s[j][3]));
        }
        mx0 = fmaxf(mx0, __shfl_xor_sync(0xffffffffu, mx0, 1));
        mx0 = fmaxf(mx0, __shfl_xor_sync(0xffffffffu, mx0, 2));
        mx1 = fmaxf(mx1, __shfl_xor_sync(0xffffffffu, mx1, 1));
        mx1 = fmaxf(mx1, __shfl_xor_sync(0xffffffffu, mx1, 2));
        float mn0 = fmaxf(m0r, mx0), mn1 = fmaxf(m1r, mx1);
        float al0 = __expf(m0r - mn0), al1 = __expf(m1r - mn1);
        float sm0 = 0.f, sm1 = 0.f;
#pragma unroll
        for (int j = 0; j < 8; ++j) {
            s[j][0] = __expf(s[j][0] - mn0);
            s[j][1] = __expf(s[j][1] - mn0);
            s[j][2] = __expf(s[j][2] - mn1);
            s[j][3] = __expf(s[j][3] - mn1);
            sm0 += s[j][0] + s[j][1];
            sm1 += s[j][2] + s[j][3];
        }
        sm0 += __shfl_xor_sync(0xffffffffu, sm0, 1);
        sm0 += __shfl_xor_sync(0xffffffffu, sm0, 2);
        sm1 += __shfl_xor_sync(0xffffffffu, sm1, 1);
        sm1 += __shfl_xor_sync(0xffffffffu, sm1, 2);
        l0r = l0r * al0 + sm0;
        l1r = l1r * al1 + sm1;
        m0r = mn0; m1r = mn1;
#pragma unroll
        for (int j = 0; j < 8; ++j) {
            O[j][0] *= al0; O[j][1] *= al0;
            O[j][2] *= al1; O[j][3] *= al1;
        }

        __syncthreads();
#pragma unroll
        for (int j = 0; j < 8; ++j) {
            int key = j * 8 + q2 * 2;
            int kc  = key >> 2;
            int pos = (kc & 8) | ((kc & 7) ^ (g & 7));
            int wrd = (wrp * 16 + g) * 64 + 4 * pos + (key & 3);
            uint32_t p0[2] = { __float_as_uint(s[j][0]), __float_as_uint(s[j][1]) };
            *(uint2*)&KP[wrd] = *(uint2*)p0;
            uint32_t p1[2] = { __float_as_uint(s[j][2]), __float_as_uint(s[j][3]) };
            *(uint2*)&KP[wrd + 8 * 64] = *(uint2*)p1;
        }
        __syncthreads();

#pragma unroll
        for (int kk = 0; kk < 8; ++kk) {
            int ck = kk * 2;
            uint32_t af[4];
            ldsm4(af[0], af[1], af[2], af[3], aswz(Kb, aRowQ, ck + cbitA));
#pragma unroll
            for (int jp = 0; jp < 4; ++jp) {
                uint32_t bf[4];
                ldsm4(bf[0], bf[1], bf[2], bf[3],
                      aswz(Vb, jp * 16 + bRowOff, ck + cbitB));
                mma_tf32(O[2 * jp],     af, &bf[0]);
                mma_tf32(O[2 * jp + 1], af, &bf[2]);
            }
        }
    }

    // epilogue: normalize, RNA-round to tf32 (feeds the out-proj GEMM exactly)
    const float inv0 = 1.f / l0r, inv1 = 1.f / l1r;
    const int row0 = b * 1024 + q0 + wrp * 16 + g;
#pragma unroll
    for (int j = 0; j < 8; ++j) {
        int d = h * 64 + j * 8 + q2 * 2;
        float2 v0 = { __uint_as_float(f2tf(O[j][0] * inv0)),
                      __uint_as_float(f2tf(O[j][1] * inv0)) };
        float2 v1 = { __uint_as_float(f2tf(O[j][2] * inv1)),
                      __uint_as_float(f2tf(O[j][3] * inv1)) };
        *(float2*)&out[(size_t)row0 * 1024 + d] = v0;
        *(float2*)&out[(size_t)(row0 + 8) * 1024 + d] = v1;
    }
}

// ---------------- LayerNorm ------------------------------------------------
__global__ __launch_bounds__(256) void ln_kernel(
    const float* __restrict__ X, const float* __restrict__ w,
    const float* __restrict__ bb, float* __restrict__ Y)
{
    const int row = blockIdx.x;
    const int t   = threadIdx.x;
    float4 x = *(const float4*)&X[(size_t)row * 1024 + t * 4];
    float s = x.x + x.y + x.z + x.w;
    float q = fmaf(x.x, x.x, fmaf(x.y, x.y, fmaf(x.z, x.z, x.w * x.w)));
#pragma unroll
    for (int off = 16; off; off >>= 1) {
        s += __shfl_xor_sync(0xffffffffu, s, off);
        q += __shfl_xor_sync(0xffffffffu, q, off);
    }
    __shared__ float ss[8], qq[8];
    const int warp = t >> 5, lane = t & 31;
    if (lane == 0) { ss[warp] = s; qq[warp] = q; }
    __syncthreads();
    float S = 0.f, Q2 = 0.f;
#pragma unroll
    for (int i = 0; i < 8; ++i) { S += ss[i]; Q2 += qq[i]; }
    const float mean = S * (1.0f / 1024.0f);
    const float var  = fmaxf(Q2 * (1.0f / 1024.0f) - mean * mean, 0.f);
    const float inv  = rsqrtf(var + 1e-12f);
    float4 wv = *(const float4*)&w[t * 4];
    float4 bv = *(const float4*)&bb[t * 4];
    float4 y;
    y.x = wv.x * (x.x - mean) * inv + bv.x;
    y.y = wv.y * (x.y - mean) * inv + bv.y;
    y.z = wv.z * (x.z - mean) * inv + bv.z;
    y.w = wv.w * (x.w - mean) * inv + bv.w;
    *(float4*)&Y[(size_t)row * 1024 + t * 4] = y;
}

// ---------------- launch ----------------------------------------------------
static constexpr int TG_SMEM = 65536;   // 4 stages x 16KB

extern "C" void kernel_launch(void* const* d_in, const int* in_sizes, int n_in,
                              void* d_out, int out_size)
{
    const float* x     = (const float*)d_in[0];
    const float* in_w  = (const float*)d_in[1];
    const float* in_b  = (const float*)d_in[2];
    const float* out_w = (const float*)d_in[3];
    const float* out_b = (const float*)d_in[4];
    const float* fc1_w = (const float*)d_in[5];
    const float* fc1_b = (const float*)d_in[6];
    const float* fc2_w = (const float*)d_in[7];
    const float* fc2_b = (const float*)d_in[8];
    const float* ln1_w = (const float*)d_in[9];
    const float* ln1_b = (const float*)d_in[10];
    const float* ln2_w = (const float*)d_in[11];
    const float* ln2_b = (const float*)d_in[12];
    const void*  pad   = d_in[13];
    float* out = (float*)d_out;

    float *qkv, *attn, *sbuf, *x1, *ff, *wq;
    int* lenv;
    cudaGetSymbolAddress((void**)&qkv,  g_qkv);
    cudaGetSymbolAddress((void**)&attn, g_attn);
    cudaGetSymbolAddress((void**)&sbuf, g_s);
    cudaGetSymbolAddress((void**)&x1,   g_x1);
    cudaGetSymbolAddress((void**)&ff,   g_ff);
    cudaGetSymbolAddress((void**)&wq,   g_wq);
    cudaGetSymbolAddress((void**)&lenv, g_len);

    float* w_in  = wq;
    float* w_out = wq + 3145728;
    float* w_f1  = wq + 4194304;
    float* w_f2  = wq + 8388608;

    static bool attr_done = false;
    if (!attr_done) {
        cudaFuncSetAttribute(tgemm_kernel<0, false>, cudaFuncAttributeMaxDynamicSharedMemorySize, TG_SMEM);
        cudaFuncSetAttribute(tgemm_kernel<1, false>, cudaFuncAttributeMaxDynamicSharedMemorySize, TG_SMEM);
        cudaFuncSetAttribute(tgemm_kernel<2, true>,  cudaFuncAttributeMaxDynamicSharedMemorySize, TG_SMEM);
        attr_done = true;
    }

    mask_len_kernel<<<1, 256>>>(pad);
    // single merged RNA weight-rounding pass
    cvt_all_kernel<<<12288, 256>>>(in_w, out_w, fc1_w, fc2_w, wq);

    // 1) qkv = x @ in_w^T + in_b           [8192, 3072]
    tgemm_kernel<0, false><<<dim3(24, 64), 256, TG_SMEM>>>(x, w_in, in_b, nullptr, qkv, 1024, 3072);
    // 2) attention -> attn (tf32-rounded)  [8192, 1024]
    attn_kernel<<<dim3(16, 16, 8), 128>>>(qkv, lenv, attn);
    // 3) s1 = attn @ out_w^T + out_b + x   [8192, 1024]  (both operands exact tf32)
    tgemm_kernel<1, false><<<dim3(8, 64), 256, TG_SMEM>>>(attn, w_out, out_b, x, sbuf, 1024, 1024);
    // 4) x1 = LN1(s1)
    ln_kernel<<<8192, 256>>>(sbuf, ln1_w, ln1_b, x1);
    // 5) ff = relu(x1 @ fc1_w^T + fc1_b) (tf32-rounded)  [8192, 4096]
    tgemm_kernel<2, true><<<dim3(32, 64), 256, TG_SMEM>>>(x1, w_f1, fc1_b, nullptr, ff, 1024, 4096);
    // 6) s2 = ff @ fc2_w^T + fc2_b + x1    [8192, 1024]  (both operands exact tf32)
    tgemm_kernel<1, false><<<dim3(8, 64), 256, TG_SMEM>>>(ff, w_f2, fc2_b, x1, sbuf, 4096, 1024);
    // 7) out = LN2(s2)
    ln_kernel<<<8192, 256>>>(sbuf, ln2_w, ln2_b, out);
}